// round 12
// baseline (speedup 1.0000x reference)
#include <cuda_runtime.h>
#include <cuda_fp16.h>
#include <cstdint>

#define NGR   20000
#define NODES 7
#define PAD   8
#define MP    (NGR*PAD)        // 160000 padded rows
#define NN    (NGR*NODES)      // 140000 real nodes
#define HID   256
#define NOPS  5

#define BM 128                 // 16 graphs (8 padded rows each)
#define BN 256                 // full HID in one CTA
#define BK 32
#define STAGES (HID/BK)        // 8
#define THREADS 512

#define ROWB   80              // bytes per smem row (32 fp16 = 64B data + 16B pad; conflict-free)
#define ACOMP  (128*ROWB)      // 10240 B per A split component
#define BCOMP  (256*ROWB)      // 20480 B per B split component
#define BOFF   (2*ACOMP)       // A planes 0..1, then B planes 0..1
#define STAGE  (2*ACOMP + 2*BCOMP)   // 61440 per stage
#define SMEM_DYN (2*STAGE)     // 122880 (covers 128x132 fp32 epilogue staging = 67584)

#define WSCALE     64.0f
#define INV_WSCALE 0.015625f
#define HH  (HID*HID)

// ---------------- device globals (no allocs allowed) ----------------
__device__ float g_H1p[(size_t)MP*HID];      // padded fp32 H1 (row 7/graph unused)
__device__ __half g_Wsp[2][2*HID*HID];       // per-layer fp16x2 split of 64*W, [n][k]
__device__ float g_qfull[(size_t)MP*NOPS];   // full H2@Wm projection (padded rows)

typedef uint32_t u32;

// ---------------- PTX helpers (plain sm_80-class features only) ----------------
__device__ __forceinline__ u32 s2u(const void* p){
    u32 a;
    asm("{ .reg .u64 t; cvta.to.shared.u64 t, %1; cvt.u32.u64 %0, t; }" : "=r"(a) : "l"(p));
    return a;
}
__device__ __forceinline__ void cp16(u32 dst, const void* src){
    asm volatile("cp.async.cg.shared.global [%0], [%1], 16;" :: "r"(dst), "l"(src));
}
#define CPCOMMIT() asm volatile("cp.async.commit_group;")
#define CPWAIT0()  asm volatile("cp.async.wait_group 0;" ::: "memory")

__device__ __forceinline__ void ldsm_x4(u32& r0,u32& r1,u32& r2,u32& r3, u32 a){
    asm volatile("ldmatrix.sync.aligned.m8n8.x4.shared.b16 {%0,%1,%2,%3}, [%4];"
                 : "=r"(r0),"=r"(r1),"=r"(r2),"=r"(r3) : "r"(a));
}
__device__ __forceinline__ void ldsm_x2(u32& r0,u32& r1, u32 a){
    asm volatile("ldmatrix.sync.aligned.m8n8.x2.shared.b16 {%0,%1}, [%2];"
                 : "=r"(r0),"=r"(r1) : "r"(a));
}
__device__ __forceinline__ void mma16816(float* c, const u32* a, const u32* b){
    asm volatile("mma.sync.aligned.m16n8k16.row.col.f32.f16.f16.f32 "
        "{%0,%1,%2,%3}, {%4,%5,%6,%7}, {%8,%9}, {%0,%1,%2,%3};"
        : "+f"(c[0]),"+f"(c[1]),"+f"(c[2]),"+f"(c[3])
        : "r"(a[0]),"r"(a[1]),"r"(a[2]),"r"(a[3]), "r"(b[0]),"r"(b[1]));
}
__device__ __forceinline__ void sts128(u32 a, u32 x, u32 y, u32 z, u32 w){
    asm volatile("st.shared.v4.b32 [%0], {%1,%2,%3,%4};"
                 :: "r"(a), "r"(x),"r"(y),"r"(z),"r"(w) : "memory");
}
// fp32 -> 2-way fp16 split of adjacent pair (lo=x, hi=y), packed f16x2
__device__ __forceinline__ void split2h(float x, float y, u32& p0, u32& p1){
    u32 hx = (u32)__half_as_ushort(__float2half_rn(x));
    u32 hy = (u32)__half_as_ushort(__float2half_rn(y));
    p0 = hx | (hy << 16);
    float rx = x - __half2float(__ushort_as_half((unsigned short)hx));
    float ry = y - __half2float(__ushort_as_half((unsigned short)hy));
    u32 gx = (u32)__half_as_ushort(__float2half_rn(rx));
    u32 gy = (u32)__half_as_ushort(__float2half_rn(ry));
    p1 = gx | (gy << 16);
}

// ====== fp16x2 3-pass HMMA GEMM, BM=128 x BN=256 x BK=32, 512 threads ======
// mode 0 (layer 1): padmap A from unpadded x; write padded fp32 H1.
// mode 1 (layer 2): A from padded fp32 H1; fused Wm projection -> full q.
__global__ __launch_bounds__(THREADS, 1)
void gemm_mma(const float* __restrict__ A, const __half* __restrict__ Wsp,
              const float* __restrict__ bias, float* __restrict__ Hf,
              const float* __restrict__ WmG, float* __restrict__ qfull, int mode)
{
    extern __shared__ __align__(128) char smem[];
    const u32 sb = s2u(smem);

    const int tid  = threadIdx.x;
    const int lane = tid & 31;
    const int warp = tid >> 5;         // 0..15
    const int wm = warp >> 2;          // 0..3  (M: 32-row slab)
    const int wn = warp & 3;           // 0..3  (N: 64-col slab)
    const int m0 = blockIdx.x * BM;

    // ---- A source row for this thread (8 fp32: row tid>>2, cols (tid&3)*8..+7)
    const int  arow_i  = tid >> 2;     // 0..127
    const int  quarter = tid & 3;
    const float* arow;
    if (mode == 0) {                   // layer 1: unpadded 7-row graphs
        int pr = m0 + arow_i, g = pr >> 3, j = pr & 7;
        arow = (j < NODES) ? (A + (size_t)(g*NODES + j) * HID) : nullptr;
    } else {
        arow = A + (size_t)(m0 + arow_i) * HID;
    }

    float4 av0, av1;

    #define LOAD_A(k0) do {                                                     \
        if (arow) { const float* ap_ = arow + (k0) + quarter*8;                 \
                    av0 = *(const float4*)(ap_);                                \
                    av1 = *(const float4*)(ap_ + 4); }                          \
        else      { av0 = make_float4(0.f,0.f,0.f,0.f); av1 = av0; }            \
    } while(0)

    #define STS_A(stb) do {                                                     \
        u32 p0[4], p1[4];                                                       \
        split2h(av0.x, av0.y, p0[0], p1[0]);                                    \
        split2h(av0.z, av0.w, p0[1], p1[1]);                                    \
        split2h(av1.x, av1.y, p0[2], p1[2]);                                    \
        split2h(av1.z, av1.w, p0[3], p1[3]);                                    \
        u32 ad = (stb) + arow_i*ROWB + quarter*16;                              \
        sts128(ad,         p0[0], p0[1], p0[2], p0[3]);                         \
        sts128(ad + ACOMP, p1[0], p1[1], p1[2], p1[3]);                         \
    } while(0)

    // B: 2048 16B-chunks per stage (2 comps x 256 rows x 4 chunks) -> 4/thread
    #define CP_B(stb, k0) do {                                                  \
        _Pragma("unroll")                                                       \
        for (int i = 0; i < 4; i++) {                                           \
            int c = tid + THREADS*i;                                            \
            int comp = c >> 10, rem = c & 1023, n = rem >> 2, q = rem & 3;      \
            u32 dst = (stb) + BOFF + comp*BCOMP + n*ROWB + q*16;                \
            const __half* src = Wsp + (size_t)comp*HH                           \
                                + (size_t)n*HID + (k0) + q*8;                   \
            cp16(dst, src);                                                     \
        }                                                                       \
        CPCOMMIT();                                                             \
    } while(0)

    // ---- prologue: stage 0
    CP_B(sb, 0);
    LOAD_A(0);
    STS_A(sb);
    CPWAIT0();
    __syncthreads();

    float acc[64];
    #pragma unroll
    for (int i = 0; i < 64; i++) acc[i] = 0.f;

    // ldmatrix lane addressing
    const int a_r  = wm*32 + (lane & 15);
    const int a_ch = lane >> 4;
    const int b_r  = wn*64 + (lane & 7);
    const int b_ch = (lane >> 3) & 1;

    #pragma unroll 1
    for (int s = 0; s < STAGES; s++) {
        const u32 cur = sb + (u32)(s & 1) * STAGE;
        const u32 nxt = sb + (u32)((s + 1) & 1) * STAGE;
        if (s + 1 < STAGES) {
            LOAD_A((s + 1) * BK);          // LDGs first (longest latency)
            CP_B(nxt, (s + 1) * BK);
        }

        #pragma unroll
        for (int kh = 0; kh < 2; kh++) {
            const u32 kb = cur + kh*32;    // 16-k half within the 32-k stage

            u32 afr[2][2][4];
            #pragma unroll
            for (int mt = 0; mt < 2; mt++)
                #pragma unroll
                for (int sp = 0; sp < 2; sp++)
                    ldsm_x4(afr[mt][sp][0], afr[mt][sp][1], afr[mt][sp][2], afr[mt][sp][3],
                            kb + sp*ACOMP + (a_r + mt*16)*ROWB + a_ch*16);

            #pragma unroll
            for (int ntp = 0; ntp < 4; ntp++) {
                u32 bfr[2][2][2];               // [h][split][2 regs]
                #pragma unroll
                for (int h = 0; h < 2; h++)
                    #pragma unroll
                    for (int sp = 0; sp < 2; sp++)
                        ldsm_x2(bfr[h][sp][0], bfr[h][sp][1],
                                kb + BOFF + sp*BCOMP + (b_r + (2*ntp + h)*8)*ROWB + b_ch*16);

                // pass 1: a0*b0
                #pragma unroll
                for (int h = 0; h < 2; h++)
                    #pragma unroll
                    for (int mt = 0; mt < 2; mt++)
                        mma16816(&acc[(mt*8 + 2*ntp + h)*4], afr[mt][0], bfr[h][0]);
                // pass 2: a0*b1
                #pragma unroll
                for (int h = 0; h < 2; h++)
                    #pragma unroll
                    for (int mt = 0; mt < 2; mt++)
                        mma16816(&acc[(mt*8 + 2*ntp + h)*4], afr[mt][0], bfr[h][1]);
                // pass 3: a1*b0
                #pragma unroll
                for (int h = 0; h < 2; h++)
                    #pragma unroll
                    for (int mt = 0; mt < 2; mt++)
                        mma16816(&acc[(mt*8 + 2*ntp + h)*4], afr[mt][1], bfr[h][0]);
            }
        }

        if (s + 1 < STAGES) {
            STS_A(nxt);
            CPWAIT0();
        }
        __syncthreads();
    }

    // ---- epilogue: two 128-col passes; Ds = 128x132 fp32 staging in stage memory
    float* Ds = (float*)smem;
    float dinv[7];
    #pragma unroll
    for (int j = 0; j < 7; j++) dinv[j] = rsqrtf((float)(j + 1));

    float pq[7*NOPS];                      // mode 1 accumulator across both halves
    #pragma unroll
    for (int t = 0; t < 7*NOPS; t++) pq[t] = 0.f;

    const int g  = (tid & 255) >> 4;       // graph in tile (16)   [tid<256 active]
    const int cg = tid & 15;               // 8-col group (16)

    #pragma unroll 1
    for (int hp = 0; hp < 2; hp++) {
        // warps owning this 128-col half write their accs
        if ((wn >> 1) == hp) {
            const int r0 = wm*32 + (lane >> 2);
            const int c0 = (wn & 1)*64 + (lane & 3)*2;
            #pragma unroll
            for (int mt = 0; mt < 2; mt++)
                #pragma unroll
                for (int nt = 0; nt < 8; nt++) {
                    const float* c = &acc[(mt*8 + nt)*4];
                    float* d = &Ds[(size_t)(r0 + mt*16)*132 + c0 + nt*8];
                    d[0] = c[0]; d[1] = c[1];
                    d[132*8 + 0] = c[2]; d[132*8 + 1] = c[3];
                }
        }
        __syncthreads();

        if (tid < 256) {
            float gv[7][8];
            #pragma unroll
            for (int i = 0; i < 7; i++) {
                float4 lo = *(float4*)&Ds[(size_t)(g*8 + i)*132 + cg*8];
                float4 hi = *(float4*)&Ds[(size_t)(g*8 + i)*132 + cg*8 + 4];
                gv[i][0]=lo.x; gv[i][1]=lo.y; gv[i][2]=lo.z; gv[i][3]=lo.w;
                gv[i][4]=hi.x; gv[i][5]=hi.y; gv[i][6]=hi.z; gv[i][7]=hi.w;
            }
            float bv[8];
            #pragma unroll
            for (int c = 0; c < 8; c++) bv[c] = bias[hp*128 + cg*8 + c];

            if (mode == 0) {
                #pragma unroll
                for (int j = 0; j < 7; j++) {
                    float v[8];
                    #pragma unroll
                    for (int c = 0; c < 8; c++) v[c] = 0.f;
                    #pragma unroll
                    for (int i = 0; i < 7; i++) {
                        if (i <= j) {
                            float cji = dinv[i] * dinv[j] * INV_WSCALE;
                            #pragma unroll
                            for (int c = 0; c < 8; c++) v[c] = fmaf(cji, gv[i][c], v[c]);
                        }
                    }
                    float4 s0, s1;
                    s0.x = fmaxf(v[0]+bv[0], 0.f); s0.y = fmaxf(v[1]+bv[1], 0.f);
                    s0.z = fmaxf(v[2]+bv[2], 0.f); s0.w = fmaxf(v[3]+bv[3], 0.f);
                    s1.x = fmaxf(v[4]+bv[4], 0.f); s1.y = fmaxf(v[5]+bv[5], 0.f);
                    s1.z = fmaxf(v[6]+bv[6], 0.f); s1.w = fmaxf(v[7]+bv[7], 0.f);
                    const size_t ob = (size_t)(m0 + g*8 + j) * HID + hp*128 + cg*8;
                    *(float4*)&Hf[ob]     = s0;
                    *(float4*)&Hf[ob + 4] = s1;
                }
            } else {
                float wreg[40];
                #pragma unroll
                for (int c = 0; c < 8; c++)
                    #pragma unroll
                    for (int o = 0; o < NOPS; o++)
                        wreg[c*NOPS + o] = __ldg(&WmG[(size_t)(hp*128 + cg*8 + c)*NOPS + o]);

                #pragma unroll
                for (int j = 0; j < 7; j++) {
                    float v[8];
                    #pragma unroll
                    for (int c = 0; c < 8; c++) v[c] = 0.f;
                    #pragma unroll
                    for (int i = 0; i < 7; i++) {
                        if (i <= j) {
                            float cji = dinv[i] * dinv[j] * INV_WSCALE;
                            #pragma unroll
                            for (int c = 0; c < 8; c++) v[c] = fmaf(cji, gv[i][c], v[c]);
                        }
                    }
                    #pragma unroll
                    for (int c = 0; c < 8; c++) {
                        float vv = fmaxf(v[c] + bv[c], 0.f);
                        #pragma unroll
                        for (int o = 0; o < NOPS; o++)
                            pq[j*NOPS + o] = fmaf(vv, wreg[c*NOPS + o], pq[j*NOPS + o]);
                    }
                }
            }
        }
        __syncthreads();                    // Ds reads done before next half overwrites
    }

    if (mode == 1 && tid < 256) {
        // reduce over the 16 cg-lanes (xor 8,4,2,1 stays inside the 16-lane group)
        #pragma unroll
        for (int t = 0; t < 7*NOPS; t++) {
            #pragma unroll
            for (int off = 8; off; off >>= 1)
                pq[t] += __shfl_xor_sync(0xFFFFFFFFu, pq[t], off);
        }
        if (cg == 0) {
            float* qp = qfull + (size_t)(m0 + g*8) * NOPS;
            #pragma unroll
            for (int t = 0; t < 7*NOPS; t++) qp[t] = pq[t];
        }
    }
    #undef LOAD_A
    #undef STS_A
    #undef CP_B
}

// ============ W -> fp16x2 split of 64*W, transposed to [n][k] ====================
__global__ void w_prep(const float* __restrict__ W1, const float* __restrict__ W2)
{
    const int layer = blockIdx.y;
    const float* W = layer ? W2 : W1;
    __half* O = g_Wsp[layer];
    const int k = blockIdx.x;
    const int n = threadIdx.x;
    float w = W[(size_t)k * HID + n] * WSCALE;
    __half c0 = __float2half_rn(w);
    float r = w - __half2float(c0);
    __half c1 = __float2half_rn(r);
    size_t o = (size_t)n * HID + k;
    O[o]      = c0;
    O[HH + o] = c1;
}

// ============ final: weighted agg over q, hard argmax ============
__global__ __launch_bounds__(224)
void op_select(const float* __restrict__ qfull, const float* __restrict__ bm,
               const float* __restrict__ gop, float* __restrict__ out)
{
    __shared__ float qs[224][NOPS];

    const int tid = threadIdx.x;
    const int node = blockIdx.x * 224 + tid;
    const int lg = tid / 7;
    const int j  = tid - lg * 7;
    const size_t prow = ((size_t)(node / 7)) * PAD + (node % 7);

    const float* q0 = qfull + prow * NOPS;
    #pragma unroll
    for (int o = 0; o < NOPS; o++) qs[tid][o] = q0[o];
    __syncthreads();

    float p[NOPS];
    #pragma unroll
    for (int o = 0; o < NOPS; o++) p[o] = bm[o];
    const float dj = rsqrtf(1.f + 0.5f * (float)j);
    for (int i = 0; i <= j; i++) {
        float c = rsqrtf(1.f + 0.5f * (float)i) * dj;
        if (i != j) c *= 0.5f;                 // edge weight 0.5; self loop 1
        #pragma unroll
        for (int o = 0; o < NOPS; o++) p[o] += c * qs[lg*7 + i][o];
    }

    float best = -3.4e38f; int arg = 0;
    #pragma unroll
    for (int o = 0; o < NOPS; o++) {
        float z = p[o] + gop[(size_t)node * NOPS + o];
        if (z > best) { best = z; arg = o; }   // strict > keeps FIRST max (jnp.argmax)
    }
    #pragma unroll
    for (int o = 0; o < NOPS; o++)
        out[(size_t)node * NOPS + o] = (o == arg) ? 1.0f : 0.0f;
}

extern "C" void kernel_launch(void* const* d_in, const int* in_sizes, int n_in,
                              void* d_out, int out_size)
{
    const float* x   = (const float*)d_in[0];
    // d_in[1] edge_index, d_in[2] batch: fixed DAG folded into closed-form coefficients
    const float* W1  = (const float*)d_in[3];
    const float* b1  = (const float*)d_in[4];
    const float* W2  = (const float*)d_in[5];
    const float* b2  = (const float*)d_in[6];
    // d_in[7] We, d_in[8] be, d_in[11] g_edge: dead — avg of 2-way softmax == 0.5 exactly
    const float* Wm  = (const float*)d_in[9];
    const float* bm  = (const float*)d_in[10];
    const float* gop = (const float*)d_in[12];
    float* out = (float*)d_out;

    float *H1p, *qfull;
    __half* Wsp;
    cudaGetSymbolAddress((void**)&H1p,   g_H1p);
    cudaGetSymbolAddress((void**)&Wsp,   g_Wsp);
    cudaGetSymbolAddress((void**)&qfull, g_qfull);

    cudaFuncSetAttribute(gemm_mma, cudaFuncAttributeMaxDynamicSharedMemorySize, SMEM_DYN);

    w_prep<<<dim3(HID, 2), HID>>>(W1, W2);

    dim3 grid(MP / BM);                  // 1250 CTAs, full HID per CTA
    gemm_mma<<<grid, THREADS, SMEM_DYN>>>(x,   Wsp,        b1, H1p,     nullptr, nullptr, 0);
    gemm_mma<<<grid, THREADS, SMEM_DYN>>>(H1p, Wsp + 2*HH, b2, nullptr, Wm,      qfull,   1);

    op_select<<<NN / 224, 224>>>(qfull, bm, gop, out);
}

// round 14
// speedup vs baseline: 1.5302x; 1.5302x over previous
#include <cuda_runtime.h>
#include <cuda.h>
#include <cuda_fp16.h>
#include <cstdint>

#define NGR   20000
#define NODES 7
#define PAD   8
#define MP    (NGR*PAD)        // 160000 padded rows
#define NN    (NGR*NODES)      // 140000 real nodes
#define HID   256
#define NOPS  5

#define BM 128                 // 16 graphs (8 padded rows each)
#define BN 128
#define BK 32
#define STAGES (HID/BK)        // 8
#define NBUF 3

#define PLANE 8192             // one 128-row x 64-byte SW64 tile
#define BUFB  (4*PLANE)        // A0,A1,B0,B1 = 32768 per stage
#define MBAR_OFF (NBUF*BUFB)   // mbarriers after buffers (and after 67584B epilogue staging)
#define SMEM_DYN (NBUF*BUFB + 64 + 1024)   // +1024 manual alignment slack

#define WSCALE     64.0f
#define INV_WSCALE 0.015625f
#define HH  (HID*HID)
#define MPH ((size_t)MP*HID)

// ---------------- device globals (no allocs allowed) ----------------
__device__ __half g_Xsp [(size_t)2*MP*HID];   // fp16x2 planes of padded X
__device__ __half g_H1sp[(size_t)2*MP*HID];   // fp16x2 planes of padded H1
__device__ __half g_Wsp[2][2*HID*HID];        // per-layer fp16x2 of 64*W, [n][k]
__device__ float g_qpart[(size_t)2*MP*NOPS];  // per-N-tile partial H2@Wm

typedef uint32_t u32;

// ---------------- PTX helpers (base sm_90-class features only) ----------------
__device__ __forceinline__ u32 s2u(const void* p){
    u32 a;
    asm("{ .reg .u64 t; cvta.to.shared.u64 t, %1; cvt.u32.u64 %0, t; }" : "=r"(a) : "l"(p));
    return a;
}
#define MBAR_INIT(a,c)  asm volatile("mbarrier.init.shared.b64 [%0], %1;" :: "r"(a), "r"(c) : "memory")
#define MBAR_EXPECT_TX(a, b) \
    asm volatile("mbarrier.arrive.expect_tx.shared.b64 _, [%0], %1;" :: "r"(a), "r"((u32)(b)) : "memory")
#define MBAR_WAIT_PARITY(mbar, parity) do {                                          \
    u32 _m = (mbar); u32 _p = (parity); u32 _done;                                   \
    asm volatile("{\n\t.reg .pred p;\n\t"                                            \
        "mbarrier.try_wait.parity.acquire.cta.shared::cta.b64 p, [%1], %2;\n\t"      \
        "selp.b32 %0, 1, 0, p;\n\t}" : "=r"(_done) : "r"(_m), "r"(_p) : "memory");   \
    if (!_done) {                                                                    \
        asm volatile("{\n\t.reg .pred P1;\n\t"                                       \
            "WL_%=:\n\t"                                                             \
            "mbarrier.try_wait.parity.acquire.cta.shared::cta.b64 P1, [%0], %1, 0x989680;\n\t" \
            "@P1 bra.uni WD_%=;\n\t"                                                 \
            "bra.uni WL_%=;\n\t"                                                     \
            "WD_%=:\n\t}" :: "r"(_m), "r"(_p) : "memory");                           \
    }                                                                                \
} while (0)

#define TMA2D(dst, map_ptr, cx, cy, mbar) \
    asm volatile("cp.async.bulk.tensor.2d.shared::cta.global.tile.mbarrier::complete_tx::bytes " \
        "[%0], [%1, {%2, %3}], [%4];" \
        :: "r"(dst), "l"(map_ptr), "r"((int)(cx)), "r"((int)(cy)), "r"(mbar) : "memory")

__device__ __forceinline__ void ldsm_x4(u32& r0,u32& r1,u32& r2,u32& r3, u32 a){
    asm volatile("ldmatrix.sync.aligned.m8n8.x4.shared.b16 {%0,%1,%2,%3}, [%4];"
                 : "=r"(r0),"=r"(r1),"=r"(r2),"=r"(r3) : "r"(a));
}
__device__ __forceinline__ void ldsm_x2(u32& r0,u32& r1, u32 a){
    asm volatile("ldmatrix.sync.aligned.m8n8.x2.shared.b16 {%0,%1}, [%2];"
                 : "=r"(r0),"=r"(r1) : "r"(a));
}
__device__ __forceinline__ void mma16816(float* c, const u32* a, const u32* b){
    asm volatile("mma.sync.aligned.m16n8k16.row.col.f32.f16.f16.f32 "
        "{%0,%1,%2,%3}, {%4,%5,%6,%7}, {%8,%9}, {%0,%1,%2,%3};"
        : "+f"(c[0]),"+f"(c[1]),"+f"(c[2]),"+f"(c[3])
        : "r"(a[0]),"r"(a[1]),"r"(a[2]),"r"(a[3]), "r"(b[0]),"r"(b[1]));
}
__device__ __forceinline__ u32 swz64(u32 off){ return off ^ ((off >> 3) & 0x30); }

// fp32 -> 2-way fp16 split of adjacent pair (lo=x, hi=y), packed f16x2
__device__ __forceinline__ void split2h(float x, float y, u32& p0, u32& p1){
    u32 hx = (u32)__half_as_ushort(__float2half_rn(x));
    u32 hy = (u32)__half_as_ushort(__float2half_rn(y));
    p0 = hx | (hy << 16);
    float rx = x - __half2float(__ushort_as_half((unsigned short)hx));
    float ry = y - __half2float(__ushort_as_half((unsigned short)hy));
    u32 gx = (u32)__half_as_ushort(__float2half_rn(rx));
    u32 gy = (u32)__half_as_ushort(__float2half_rn(ry));
    p1 = gx | (gy << 16);
}

// ============ X -> padded fp16x2 planes ============
__global__ __launch_bounds__(256)
void split_x(const float* __restrict__ x)
{
    const int g = blockIdx.x, t = threadIdx.x;
    const int cp = (t & 127) * 2;
    const int rh = t >> 7;
    #pragma unroll
    for (int rr = 0; rr < 4; rr++) {
        int row = rr*2 + rh;
        u32 p0 = 0, p1 = 0;
        if (row < NODES) {
            const float* s = x + ((size_t)g*NODES + row) * HID + cp;
            split2h(s[0], s[1], p0, p1);
        }
        size_t o = ((size_t)g*PAD + row) * HID + cp;
        *(u32*)(g_Xsp + o)        = p0;
        *(u32*)(g_Xsp + MPH + o)  = p1;
    }
}

// ====== fp16x2 3-pass HMMA GEMM, all operands via TMA, pass-outer MMA order ======
// mode 0 (layer 1): write H1 as fp16x2 planes.  mode 1 (layer 2): fused Wm -> qpart.
__global__ __launch_bounds__(256, 2)
void gemm_mma(const __grid_constant__ CUtensorMap tA,
              const __grid_constant__ CUtensorMap tB, int nbase,
              const float* __restrict__ bias, __half* __restrict__ Hsp,
              const float* __restrict__ WmG, float* __restrict__ qpart, int mode)
{
    extern __shared__ __align__(128) char smem[];
    const u32 sb_raw = s2u(smem);
    const u32 sb = (sb_raw + 1023u) & ~1023u;      // 1KB-align: TMA dst + SW64 atom base
    char* smemA = smem + (sb - sb_raw);            // aligned alias for epilogue staging
    const u32 mb = sb + MBAR_OFF;                  // mbarriers live in dynamic smem

    const int tid  = threadIdx.x;
    const int lane = tid & 31;
    const int warp = tid >> 5;
    const int wm = warp >> 1;          // 0..3  (M: 32-row slab)
    const int wn = warp & 1;           // 0..1  (N: 64-col slab)
    const int m0 = blockIdx.y * BM;
    const int n0 = blockIdx.x * BN;

    const void* pA = (const void*)&tA;
    const void* pB = (const void*)&tB;

    if (tid == 0) {
        #pragma unroll
        for (int b = 0; b < NBUF; b++) MBAR_INIT(mb + b*8, 1);
    }
    __syncthreads();

    #define ISSUE(s_) do {                                                   \
        u32 bb_ = sb + (u32)((s_) % NBUF) * BUFB;                            \
        u32 mb_ = mb + ((s_) % NBUF) * 8;                                    \
        MBAR_EXPECT_TX(mb_, BUFB);                                           \
        TMA2D(bb_,             pA, (s_)*BK, m0,               mb_);          \
        TMA2D(bb_ + PLANE,     pA, (s_)*BK, MP + m0,          mb_);          \
        TMA2D(bb_ + 2*PLANE,   pB, (s_)*BK, nbase + n0,       mb_);          \
        TMA2D(bb_ + 3*PLANE,   pB, (s_)*BK, nbase + 256 + n0, mb_);          \
    } while(0)

    if (tid == 0) { ISSUE(0); ISSUE(1); ISSUE(2); }

    float acc[64];
    #pragma unroll
    for (int i = 0; i < 64; i++) acc[i] = 0.f;

    // ldmatrix lane addressing (SW64 swizzled 64B rows)
    const u32 a_base = (u32)((wm*32 + (lane & 15)) * 64 + (lane >> 4) * 16);
    const u32 b_base = (u32)((wn*64 + (lane & 7)) * 64 + ((lane >> 3) & 1) * 16);

    #pragma unroll 1
    for (int s = 0; s < STAGES; s++) {
        MBAR_WAIT_PARITY(mb + (s % NBUF)*8, (u32)((s / NBUF) & 1));
        const u32 bb = sb + (u32)(s % NBUF) * BUFB;

        #pragma unroll
        for (int kh = 0; kh < 2; kh++) {
            u32 afr[2][2][4];
            #pragma unroll
            for (int mt = 0; mt < 2; mt++)
                #pragma unroll
                for (int sp = 0; sp < 2; sp++)
                    ldsm_x4(afr[mt][sp][0], afr[mt][sp][1], afr[mt][sp][2], afr[mt][sp][3],
                            bb + sp*PLANE + swz64(a_base + mt*16*64 + kh*32));

            #pragma unroll
            for (int ntp = 0; ntp < 4; ntp++) {
                u32 bfr[2][2][2];               // [h][split][2 regs]
                #pragma unroll
                for (int h = 0; h < 2; h++)
                    #pragma unroll
                    for (int sp = 0; sp < 2; sp++)
                        ldsm_x2(bfr[h][sp][0], bfr[h][sp][1],
                                bb + (2 + sp)*PLANE +
                                swz64(b_base + (2*ntp + h)*8*64 + kh*32));

                // pass 1: a0*b0
                #pragma unroll
                for (int h = 0; h < 2; h++)
                    #pragma unroll
                    for (int mt = 0; mt < 2; mt++)
                        mma16816(&acc[(mt*8 + 2*ntp + h)*4], afr[mt][0], bfr[h][0]);
                // pass 2: a0*b1
                #pragma unroll
                for (int h = 0; h < 2; h++)
                    #pragma unroll
                    for (int mt = 0; mt < 2; mt++)
                        mma16816(&acc[(mt*8 + 2*ntp + h)*4], afr[mt][0], bfr[h][1]);
                // pass 3: a1*b0
                #pragma unroll
                for (int h = 0; h < 2; h++)
                    #pragma unroll
                    for (int mt = 0; mt < 2; mt++)
                        mma16816(&acc[(mt*8 + 2*ntp + h)*4], afr[mt][1], bfr[h][0]);
            }
        }

        __syncthreads();                       // all warps done with buffer s%NBUF
        if (tid == 0 && s + NBUF < STAGES) ISSUE(s + NBUF);
    }
    #undef ISSUE

    // ---- epilogue: accs -> smem, GCN agg (x1/64) + bias + relu
    float* Ds = (float*)smemA;                 // [128][132], aligned base
    {
        const int r0 = wm*32 + (lane >> 2);
        const int c0 = wn*64 + (lane & 3)*2;
        #pragma unroll
        for (int mt = 0; mt < 2; mt++)
            #pragma unroll
            for (int nt = 0; nt < 8; nt++) {
                const float* c = &acc[(mt*8 + nt)*4];
                float* d = &Ds[(size_t)(r0 + mt*16)*132 + c0 + nt*8];
                d[0] = c[0]; d[1] = c[1];
                d[132*8 + 0] = c[2]; d[132*8 + 1] = c[3];
            }
    }
    __syncthreads();

    {
        const int g  = tid >> 4;               // graph in tile (16)
        const int cg = tid & 15;               // 8-col group (16)
        float gv[7][8];
        #pragma unroll
        for (int i = 0; i < 7; i++) {
            float4 lo = *(float4*)&Ds[(size_t)(g*8 + i)*132 + cg*8];
            float4 hi = *(float4*)&Ds[(size_t)(g*8 + i)*132 + cg*8 + 4];
            gv[i][0]=lo.x; gv[i][1]=lo.y; gv[i][2]=lo.z; gv[i][3]=lo.w;
            gv[i][4]=hi.x; gv[i][5]=hi.y; gv[i][6]=hi.z; gv[i][7]=hi.w;
        }
        float dinv[7];
        #pragma unroll
        for (int j = 0; j < 7; j++) dinv[j] = rsqrtf((float)(j + 1));
        float bv[8];
        #pragma unroll
        for (int c = 0; c < 8; c++) bv[c] = bias[n0 + cg*8 + c];

        if (mode == 0) {
            // ---- layer 1: write fp16x2 planes of padded H1
            #pragma unroll
            for (int j = 0; j < 7; j++) {
                float v[8];
                #pragma unroll
                for (int c = 0; c < 8; c++) v[c] = 0.f;
                #pragma unroll
                for (int i = 0; i < 7; i++) {
                    if (i <= j) {
                        float cji = dinv[i] * dinv[j] * INV_WSCALE;
                        #pragma unroll
                        for (int c = 0; c < 8; c++) v[c] = fmaf(cji, gv[i][c], v[c]);
                    }
                }
                #pragma unroll
                for (int c = 0; c < 8; c++) v[c] = fmaxf(v[c] + bv[c], 0.f);

                u32 p0[4], p1[4];
                split2h(v[0], v[1], p0[0], p1[0]);
                split2h(v[2], v[3], p0[1], p1[1]);
                split2h(v[4], v[5], p0[2], p1[2]);
                split2h(v[6], v[7], p0[3], p1[3]);
                const size_t ob = (size_t)(m0 + g*8 + j) * HID + n0 + cg*8;
                *(uint4*)(Hsp + ob)       = make_uint4(p0[0], p0[1], p0[2], p0[3]);
                *(uint4*)(Hsp + MPH + ob) = make_uint4(p1[0], p1[1], p1[2], p1[3]);
            }
            {   // pad row 7 must be zero for layer-2 TMA loads
                const size_t ob = (size_t)(m0 + g*8 + 7) * HID + n0 + cg*8;
                uint4 z = make_uint4(0,0,0,0);
                *(uint4*)(Hsp + ob)       = z;
                *(uint4*)(Hsp + MPH + ob) = z;
            }
        } else {
            // ---- layer 2: fused Wm projection -> qpart (no H2 materialization)
            float wreg[40];
            #pragma unroll
            for (int c = 0; c < 8; c++)
                #pragma unroll
                for (int o = 0; o < NOPS; o++)
                    wreg[c*NOPS + o] = __ldg(&WmG[(size_t)(n0 + cg*8 + c)*NOPS + o]);

            float pq[7*NOPS];
            #pragma unroll
            for (int t = 0; t < 7*NOPS; t++) pq[t] = 0.f;

            #pragma unroll
            for (int j = 0; j < 7; j++) {
                float v[8];
                #pragma unroll
                for (int c = 0; c < 8; c++) v[c] = 0.f;
                #pragma unroll
                for (int i = 0; i < 7; i++) {
                    if (i <= j) {
                        float cji = dinv[i] * dinv[j] * INV_WSCALE;
                        #pragma unroll
                        for (int c = 0; c < 8; c++) v[c] = fmaf(cji, gv[i][c], v[c]);
                    }
                }
                #pragma unroll
                for (int c = 0; c < 8; c++) {
                    float vv = fmaxf(v[c] + bv[c], 0.f);
                    #pragma unroll
                    for (int o = 0; o < NOPS; o++)
                        pq[j*NOPS + o] = fmaf(vv, wreg[c*NOPS + o], pq[j*NOPS + o]);
                }
            }

            #pragma unroll
            for (int t = 0; t < 7*NOPS; t++) {
                #pragma unroll
                for (int off = 8; off; off >>= 1)
                    pq[t] += __shfl_xor_sync(0xFFFFFFFFu, pq[t], off);
            }
            if (cg == 0) {
                float* qp = qpart + (size_t)blockIdx.x * MP * NOPS
                                  + (size_t)(m0 + g*8) * NOPS;
                #pragma unroll
                for (int t = 0; t < 7*NOPS; t++) qp[t] = pq[t];
            }
        }
    }
}

// ============ W -> fp16x2 split of 64*W, transposed to [n][k] ====================
__global__ void w_prep(const float* __restrict__ W1, const float* __restrict__ W2)
{
    const int layer = blockIdx.y;
    const float* W = layer ? W2 : W1;
    __half* O = g_Wsp[layer];
    const int k = blockIdx.x;
    const int n = threadIdx.x;
    float w = W[(size_t)k * HID + n] * WSCALE;
    __half c0 = __float2half_rn(w);
    float r = w - __half2float(c0);
    __half c1 = __float2half_rn(r);
    size_t o = (size_t)n * HID + k;
    O[o]      = c0;
    O[HH + o] = c1;
}

// ============ final: combine q partials, weighted agg, hard argmax ============
__global__ __launch_bounds__(224)
void op_select(const float* __restrict__ qpart, const float* __restrict__ bm,
               const float* __restrict__ gop, float* __restrict__ out)
{
    __shared__ float qs[224][NOPS];

    const int tid = threadIdx.x;
    const int node = blockIdx.x * 224 + tid;
    const int lg = tid / 7;
    const int j  = tid - lg * 7;
    const size_t prow = ((size_t)(node / 7)) * PAD + (node % 7);

    const float* q0 = qpart + prow * NOPS;
    const float* q1 = qpart + (size_t)MP * NOPS + prow * NOPS;
    #pragma unroll
    for (int o = 0; o < NOPS; o++) qs[tid][o] = q0[o] + q1[o];
    __syncthreads();

    float p[NOPS];
    #pragma unroll
    for (int o = 0; o < NOPS; o++) p[o] = bm[o];
    const float dj = rsqrtf(1.f + 0.5f * (float)j);
    for (int i = 0; i <= j; i++) {
        float c = rsqrtf(1.f + 0.5f * (float)i) * dj;
        if (i != j) c *= 0.5f;                 // edge weight 0.5; self loop 1
        #pragma unroll
        for (int o = 0; o < NOPS; o++) p[o] += c * qs[lg*7 + i][o];
    }

    float best = -3.4e38f; int arg = 0;
    #pragma unroll
    for (int o = 0; o < NOPS; o++) {
        float z = p[o] + gop[(size_t)node * NOPS + o];
        if (z > best) { best = z; arg = o; }   // strict > keeps FIRST max (jnp.argmax)
    }
    #pragma unroll
    for (int o = 0; o < NOPS; o++)
        out[(size_t)node * NOPS + o] = (o == arg) ? 1.0f : 0.0f;
}

// ---------------- host: tensormap encoding via driver entry point ----------------
typedef CUresult (*TmapEncodeFn)(CUtensorMap*, CUtensorMapDataType, cuuint32_t, void*,
    const cuuint64_t*, const cuuint64_t*, const cuuint32_t*, const cuuint32_t*,
    CUtensorMapInterleave, CUtensorMapSwizzle, CUtensorMapL2promotion, CUtensorMapFloatOOBfill);

static TmapEncodeFn get_encode_fn()
{
    static TmapEncodeFn fn = nullptr;
    if (!fn) {
        void* p = nullptr;
        cudaDriverEntryPointQueryResult qr;
#if CUDART_VERSION >= 12050
        cudaGetDriverEntryPointByVersion("cuTensorMapEncodeTiled", &p, 12000,
                                         cudaEnableDefault, &qr);
#else
        cudaGetDriverEntryPoint("cuTensorMapEncodeTiled", &p, cudaEnableDefault, &qr);
#endif
        fn = (TmapEncodeFn)p;
    }
    return fn;
}

static void encode_2d(TmapEncodeFn fn, CUtensorMap* m, void* base, unsigned long long rows)
{
    cuuint64_t dims[2]    = {HID, rows};
    cuuint64_t strides[1] = {HID * 2};         // bytes between rows
    cuuint32_t box[2]     = {BK, BM};          // 32 fp16 (64 B) x 128 rows
    cuuint32_t es[2]      = {1, 1};
    fn(m, CU_TENSOR_MAP_DATA_TYPE_FLOAT16, 2, base, dims, strides, box, es,
       CU_TENSOR_MAP_INTERLEAVE_NONE, CU_TENSOR_MAP_SWIZZLE_64B,
       CU_TENSOR_MAP_L2_PROMOTION_L2_128B, CU_TENSOR_MAP_FLOAT_OOB_FILL_NONE);
}

extern "C" void kernel_launch(void* const* d_in, const int* in_sizes, int n_in,
                              void* d_out, int out_size)
{
    const float* x   = (const float*)d_in[0];
    // d_in[1] edge_index, d_in[2] batch: fixed DAG folded into closed-form coefficients
    const float* W1  = (const float*)d_in[3];
    const float* b1  = (const float*)d_in[4];
    const float* W2  = (const float*)d_in[5];
    const float* b2  = (const float*)d_in[6];
    // d_in[7] We, d_in[8] be, d_in[11] g_edge: dead — avg of 2-way softmax == 0.5 exactly
    const float* Wm  = (const float*)d_in[9];
    const float* bm  = (const float*)d_in[10];
    const float* gop = (const float*)d_in[12];
    float* out = (float*)d_out;

    __half *Xsp, *H1sp, *Wsp;
    float* qpart;
    cudaGetSymbolAddress((void**)&Xsp,   g_Xsp);
    cudaGetSymbolAddress((void**)&H1sp,  g_H1sp);
    cudaGetSymbolAddress((void**)&Wsp,   g_Wsp);
    cudaGetSymbolAddress((void**)&qpart, g_qpart);

    TmapEncodeFn fn = get_encode_fn();
    CUtensorMap tX, tH, tW;
    encode_2d(fn, &tX, Xsp,  2ull*MP);   // rows: comp*MP + m
    encode_2d(fn, &tH, H1sp, 2ull*MP);
    encode_2d(fn, &tW, Wsp,  1024ull);   // rows: layer*512 + comp*256 + n

    cudaFuncSetAttribute(gemm_mma, cudaFuncAttributeMaxDynamicSharedMemorySize, SMEM_DYN);

    split_x<<<NGR, 256>>>(x);
    w_prep<<<dim3(HID, 2), HID>>>(W1, W2);

    dim3 grid(HID / BN, MP / BM);        // (2, 1250)
    gemm_mma<<<grid, 256, SMEM_DYN>>>(tX, tW, 0,   b1, H1sp,    nullptr, nullptr, 0);
    gemm_mma<<<grid, 256, SMEM_DYN>>>(tH, tW, 512, b2, nullptr, Wm,      qpart,   1);

    op_select<<<NN / 224, 224>>>(qpart, bm, gop, out);
}

// round 15
// speedup vs baseline: 1.5552x; 1.0163x over previous
#include <cuda_runtime.h>
#include <cuda.h>
#include <cuda_fp16.h>
#include <cstdint>

#define NGR   20000
#define NODES 7
#define PAD   8
#define MP    (NGR*PAD)        // 160000 padded rows
#define NN    (NGR*NODES)      // 140000 real nodes
#define HID   256
#define NOPS  5

#define BM 128                 // 16 graphs (8 padded rows each)
#define BN 128
#define BK 32
#define STAGES (HID/BK)        // 8
#define NBUF 3

#define PLANE 8192             // one 128-row x 64-byte SW64 tile
#define BUFB  (4*PLANE)        // A0,A1,B0,B1 = 32768 per stage
#define MBAR_OFF (NBUF*BUFB)   // mbarriers after buffers (and after 67584B epilogue staging)
#define SMEM_DYN (NBUF*BUFB + 64 + 1024)   // +1024 manual alignment slack

#define WSCALE     64.0f
#define INV_WSCALE 0.015625f
#define HH  (HID*HID)
#define MPH ((size_t)MP*HID)

// ---------------- device globals (no allocs allowed) ----------------
__device__ __half g_Xsp [(size_t)2*MP*HID];   // fp16x2 planes of padded X
__device__ __half g_H1sp[(size_t)2*MP*HID];   // fp16x2 planes of padded H1
__device__ __half g_Wsp[2][2*HID*HID];        // per-layer fp16x2 of 64*W, [n][k]
__device__ float g_qpart[(size_t)2*MP*NOPS];  // per-N-tile partial H2@Wm

typedef uint32_t u32;

// ---------------- PTX helpers (base sm_90-class features only) ----------------
__device__ __forceinline__ u32 s2u(const void* p){
    u32 a;
    asm("{ .reg .u64 t; cvta.to.shared.u64 t, %1; cvt.u32.u64 %0, t; }" : "=r"(a) : "l"(p));
    return a;
}
#define MBAR_INIT(a,c)  asm volatile("mbarrier.init.shared.b64 [%0], %1;" :: "r"(a), "r"(c) : "memory")
#define MBAR_EXPECT_TX(a, b) \
    asm volatile("mbarrier.arrive.expect_tx.shared.b64 _, [%0], %1;" :: "r"(a), "r"((u32)(b)) : "memory")
#define MBAR_WAIT_PARITY(mbar, parity) do {                                          \
    u32 _m = (mbar); u32 _p = (parity); u32 _done;                                   \
    asm volatile("{\n\t.reg .pred p;\n\t"                                            \
        "mbarrier.try_wait.parity.acquire.cta.shared::cta.b64 p, [%1], %2;\n\t"      \
        "selp.b32 %0, 1, 0, p;\n\t}" : "=r"(_done) : "r"(_m), "r"(_p) : "memory");   \
    if (!_done) {                                                                    \
        asm volatile("{\n\t.reg .pred P1;\n\t"                                       \
            "WL_%=:\n\t"                                                             \
            "mbarrier.try_wait.parity.acquire.cta.shared::cta.b64 P1, [%0], %1, 0x989680;\n\t" \
            "@P1 bra.uni WD_%=;\n\t"                                                 \
            "bra.uni WL_%=;\n\t"                                                     \
            "WD_%=:\n\t}" :: "r"(_m), "r"(_p) : "memory");                           \
    }                                                                                \
} while (0)

#define TMA2D(dst, map_ptr, cx, cy, mbar) \
    asm volatile("cp.async.bulk.tensor.2d.shared::cta.global.tile.mbarrier::complete_tx::bytes " \
        "[%0], [%1, {%2, %3}], [%4];" \
        :: "r"(dst), "l"(map_ptr), "r"((int)(cx)), "r"((int)(cy)), "r"(mbar) : "memory")

__device__ __forceinline__ void ldsm_x4(u32& r0,u32& r1,u32& r2,u32& r3, u32 a){
    asm volatile("ldmatrix.sync.aligned.m8n8.x4.shared.b16 {%0,%1,%2,%3}, [%4];"
                 : "=r"(r0),"=r"(r1),"=r"(r2),"=r"(r3) : "r"(a));
}
__device__ __forceinline__ void mma16816(float* c, const u32* a, const u32* b){
    asm volatile("mma.sync.aligned.m16n8k16.row.col.f32.f16.f16.f32 "
        "{%0,%1,%2,%3}, {%4,%5,%6,%7}, {%8,%9}, {%0,%1,%2,%3};"
        : "+f"(c[0]),"+f"(c[1]),"+f"(c[2]),"+f"(c[3])
        : "r"(a[0]),"r"(a[1]),"r"(a[2]),"r"(a[3]), "r"(b[0]),"r"(b[1]));
}
__device__ __forceinline__ u32 swz64(u32 off){ return off ^ ((off >> 3) & 0x30); }

// fp32 -> 2-way fp16 split of adjacent pair (lo=x, hi=y), packed f16x2
__device__ __forceinline__ void split2h(float x, float y, u32& p0, u32& p1){
    u32 hx = (u32)__half_as_ushort(__float2half_rn(x));
    u32 hy = (u32)__half_as_ushort(__float2half_rn(y));
    p0 = hx | (hy << 16);
    float rx = x - __half2float(__ushort_as_half((unsigned short)hx));
    float ry = y - __half2float(__ushort_as_half((unsigned short)hy));
    u32 gx = (u32)__half_as_ushort(__float2half_rn(rx));
    u32 gy = (u32)__half_as_ushort(__float2half_rn(ry));
    p1 = gx | (gy << 16);
}

// ============ X -> padded fp16x2 planes ============
__global__ __launch_bounds__(256)
void split_x(const float* __restrict__ x)
{
    const int g = blockIdx.x, t = threadIdx.x;
    const int cp = (t & 127) * 2;
    const int rh = t >> 7;
    #pragma unroll
    for (int rr = 0; rr < 4; rr++) {
        int row = rr*2 + rh;
        u32 p0 = 0, p1 = 0;
        if (row < NODES) {
            const float* s = x + ((size_t)g*NODES + row) * HID + cp;
            split2h(s[0], s[1], p0, p1);
        }
        size_t o = ((size_t)g*PAD + row) * HID + cp;
        *(u32*)(g_Xsp + o)        = p0;
        *(u32*)(g_Xsp + MPH + o)  = p1;
    }
}

// ====== fp16x2 3-pass HMMA GEMM, all operands via TMA, paired-x4 B loads ======
// mode 0 (layer 1): write H1 as fp16x2 planes.  mode 1 (layer 2): fused Wm -> qpart.
__global__ __launch_bounds__(256, 2)
void gemm_mma(const __grid_constant__ CUtensorMap tA,
              const __grid_constant__ CUtensorMap tB, int nbase,
              const float* __restrict__ bias, __half* __restrict__ Hsp,
              const float* __restrict__ WmG, float* __restrict__ qpart, int mode)
{
    extern __shared__ __align__(128) char smem[];
    const u32 sb_raw = s2u(smem);
    const u32 sb = (sb_raw + 1023u) & ~1023u;      // 1KB-align: TMA dst + SW64 atom base
    char* smemA = smem + (sb - sb_raw);            // aligned alias for epilogue staging
    const u32 mb = sb + MBAR_OFF;                  // mbarriers live in dynamic smem

    const int tid  = threadIdx.x;
    const int lane = tid & 31;
    const int warp = tid >> 5;
    const int wm = warp >> 1;          // 0..3  (M: 32-row slab)
    const int wn = warp & 1;           // 0..1  (N: 64-col slab)
    const int m0 = blockIdx.y * BM;
    const int n0 = blockIdx.x * BN;

    const void* pA = (const void*)&tA;
    const void* pB = (const void*)&tB;

    if (tid == 0) {
        #pragma unroll
        for (int b = 0; b < NBUF; b++) MBAR_INIT(mb + b*8, 1);
    }
    __syncthreads();

    #define ISSUE(s_) do {                                                   \
        u32 bb_ = sb + (u32)((s_) % NBUF) * BUFB;                            \
        u32 mb_ = mb + ((s_) % NBUF) * 8;                                    \
        MBAR_EXPECT_TX(mb_, BUFB);                                           \
        TMA2D(bb_,             pA, (s_)*BK, m0,               mb_);          \
        TMA2D(bb_ + PLANE,     pA, (s_)*BK, MP + m0,          mb_);          \
        TMA2D(bb_ + 2*PLANE,   pB, (s_)*BK, nbase + n0,       mb_);          \
        TMA2D(bb_ + 3*PLANE,   pB, (s_)*BK, nbase + 256 + n0, mb_);          \
    } while(0)

    if (tid == 0) { ISSUE(0); ISSUE(1); ISSUE(2); }

    float acc[64];
    #pragma unroll
    for (int i = 0; i < 64; i++) acc[i] = 0.f;

    // ldmatrix lane addressing (SW64 swizzled 64B rows)
    const u32 a_base = (u32)((wm*32 + (lane & 15)) * 64 + (lane >> 4) * 16);
    // B paired-x4: lanes 0-7 -> (nt0,k0-7), 8-15 -> (nt0,k8-15), 16-23 -> (nt1,k0-7), 24-31 -> (nt1,k8-15)
    const u32 b_base = (u32)((wn*64 + (lane & 7) + ((lane >> 4) << 3)) * 64 + ((lane >> 3) & 1) * 16);

    #pragma unroll 1
    for (int s = 0; s < STAGES; s++) {
        MBAR_WAIT_PARITY(mb + (s % NBUF)*8, (u32)((s / NBUF) & 1));
        const u32 bb = sb + (u32)(s % NBUF) * BUFB;

        #pragma unroll
        for (int kh = 0; kh < 2; kh++) {
            u32 afr[2][2][4];
            #pragma unroll
            for (int mt = 0; mt < 2; mt++)
                #pragma unroll
                for (int sp = 0; sp < 2; sp++)
                    ldsm_x4(afr[mt][sp][0], afr[mt][sp][1], afr[mt][sp][2], afr[mt][sp][3],
                            bb + sp*PLANE + swz64(a_base + mt*16*64 + kh*32));

            #pragma unroll
            for (int ntp = 0; ntp < 4; ntp++) {
                u32 bfr[2][2][2];               // [h][split][2 regs]
                #pragma unroll
                for (int sp = 0; sp < 2; sp++)
                    ldsm_x4(bfr[0][sp][0], bfr[0][sp][1], bfr[1][sp][0], bfr[1][sp][1],
                            bb + (2 + sp)*PLANE + swz64(b_base + ntp*16*64 + kh*32));

                // pass 1: a0*b0
                #pragma unroll
                for (int h = 0; h < 2; h++)
                    #pragma unroll
                    for (int mt = 0; mt < 2; mt++)
                        mma16816(&acc[(mt*8 + 2*ntp + h)*4], afr[mt][0], bfr[h][0]);
                // pass 2: a0*b1
                #pragma unroll
                for (int h = 0; h < 2; h++)
                    #pragma unroll
                    for (int mt = 0; mt < 2; mt++)
                        mma16816(&acc[(mt*8 + 2*ntp + h)*4], afr[mt][0], bfr[h][1]);
                // pass 3: a1*b0
                #pragma unroll
                for (int h = 0; h < 2; h++)
                    #pragma unroll
                    for (int mt = 0; mt < 2; mt++)
                        mma16816(&acc[(mt*8 + 2*ntp + h)*4], afr[mt][1], bfr[h][0]);
            }
        }

        __syncthreads();                       // all warps done with buffer s%NBUF
        if (tid == 0 && s + NBUF < STAGES) ISSUE(s + NBUF);
    }
    #undef ISSUE

    // ---- epilogue: accs -> smem, GCN agg (x1/64) + bias + relu
    float* Ds = (float*)smemA;                 // [128][132], aligned base
    {
        const int r0 = wm*32 + (lane >> 2);
        const int c0 = wn*64 + (lane & 3)*2;
        #pragma unroll
        for (int mt = 0; mt < 2; mt++)
            #pragma unroll
            for (int nt = 0; nt < 8; nt++) {
                const float* c = &acc[(mt*8 + nt)*4];
                float* d = &Ds[(size_t)(r0 + mt*16)*132 + c0 + nt*8];
                d[0] = c[0]; d[1] = c[1];
                d[132*8 + 0] = c[2]; d[132*8 + 1] = c[3];
            }
    }
    __syncthreads();

    {
        const int g  = tid >> 4;               // graph in tile (16)
        const int cg = tid & 15;               // 8-col group (16)
        float gv[7][8];
        #pragma unroll
        for (int i = 0; i < 7; i++) {
            float4 lo = *(float4*)&Ds[(size_t)(g*8 + i)*132 + cg*8];
            float4 hi = *(float4*)&Ds[(size_t)(g*8 + i)*132 + cg*8 + 4];
            gv[i][0]=lo.x; gv[i][1]=lo.y; gv[i][2]=lo.z; gv[i][3]=lo.w;
            gv[i][4]=hi.x; gv[i][5]=hi.y; gv[i][6]=hi.z; gv[i][7]=hi.w;
        }
        float dinv[7];
        #pragma unroll
        for (int j = 0; j < 7; j++) dinv[j] = rsqrtf((float)(j + 1));
        float bv[8];
        #pragma unroll
        for (int c = 0; c < 8; c++) bv[c] = bias[n0 + cg*8 + c];

        if (mode == 0) {
            // ---- layer 1: write fp16x2 planes of padded H1
            #pragma unroll
            for (int j = 0; j < 7; j++) {
                float v[8];
                #pragma unroll
                for (int c = 0; c < 8; c++) v[c] = 0.f;
                #pragma unroll
                for (int i = 0; i < 7; i++) {
                    if (i <= j) {
                        float cji = dinv[i] * dinv[j] * INV_WSCALE;
                        #pragma unroll
                        for (int c = 0; c < 8; c++) v[c] = fmaf(cji, gv[i][c], v[c]);
                    }
                }
                #pragma unroll
                for (int c = 0; c < 8; c++) v[c] = fmaxf(v[c] + bv[c], 0.f);

                u32 p0[4], p1[4];
                split2h(v[0], v[1], p0[0], p1[0]);
                split2h(v[2], v[3], p0[1], p1[1]);
                split2h(v[4], v[5], p0[2], p1[2]);
                split2h(v[6], v[7], p0[3], p1[3]);
                const size_t ob = (size_t)(m0 + g*8 + j) * HID + n0 + cg*8;
                *(uint4*)(Hsp + ob)       = make_uint4(p0[0], p0[1], p0[2], p0[3]);
                *(uint4*)(Hsp + MPH + ob) = make_uint4(p1[0], p1[1], p1[2], p1[3]);
            }
            {   // pad row 7 must be zero for layer-2 TMA loads
                const size_t ob = (size_t)(m0 + g*8 + 7) * HID + n0 + cg*8;
                uint4 z = make_uint4(0,0,0,0);
                *(uint4*)(Hsp + ob)       = z;
                *(uint4*)(Hsp + MPH + ob) = z;
            }
        } else {
            // ---- layer 2: fused Wm projection -> qpart (no H2 materialization)
            float wreg[40];
            #pragma unroll
            for (int c = 0; c < 8; c++)
                #pragma unroll
                for (int o = 0; o < NOPS; o++)
                    wreg[c*NOPS + o] = __ldg(&WmG[(size_t)(n0 + cg*8 + c)*NOPS + o]);

            float pq[7*NOPS];
            #pragma unroll
            for (int t = 0; t < 7*NOPS; t++) pq[t] = 0.f;

            #pragma unroll
            for (int j = 0; j < 7; j++) {
                float v[8];
                #pragma unroll
                for (int c = 0; c < 8; c++) v[c] = 0.f;
                #pragma unroll
                for (int i = 0; i < 7; i++) {
                    if (i <= j) {
                        float cji = dinv[i] * dinv[j] * INV_WSCALE;
                        #pragma unroll
                        for (int c = 0; c < 8; c++) v[c] = fmaf(cji, gv[i][c], v[c]);
                    }
                }
                #pragma unroll
                for (int c = 0; c < 8; c++) {
                    float vv = fmaxf(v[c] + bv[c], 0.f);
                    #pragma unroll
                    for (int o = 0; o < NOPS; o++)
                        pq[j*NOPS + o] = fmaf(vv, wreg[c*NOPS + o], pq[j*NOPS + o]);
                }
            }

            #pragma unroll
            for (int t = 0; t < 7*NOPS; t++) {
                #pragma unroll
                for (int off = 8; off; off >>= 1)
                    pq[t] += __shfl_xor_sync(0xFFFFFFFFu, pq[t], off);
            }
            if (cg == 0) {
                float* qp = qpart + (size_t)blockIdx.x * MP * NOPS
                                  + (size_t)(m0 + g*8) * NOPS;
                #pragma unroll
                for (int t = 0; t < 7*NOPS; t++) qp[t] = pq[t];
            }
        }
    }
}

// ============ W -> fp16x2 split of 64*W, transposed to [n][k] ====================
__global__ void w_prep(const float* __restrict__ W1, const float* __restrict__ W2)
{
    const int layer = blockIdx.y;
    const float* W = layer ? W2 : W1;
    __half* O = g_Wsp[layer];
    const int k = blockIdx.x;
    const int n = threadIdx.x;
    float w = W[(size_t)k * HID + n] * WSCALE;
    __half c0 = __float2half_rn(w);
    float r = w - __half2float(c0);
    __half c1 = __float2half_rn(r);
    size_t o = (size_t)n * HID + k;
    O[o]      = c0;
    O[HH + o] = c1;
}

// ============ final: combine q partials, weighted agg, hard argmax ============
__global__ __launch_bounds__(224)
void op_select(const float* __restrict__ qpart, const float* __restrict__ bm,
               const float* __restrict__ gop, float* __restrict__ out)
{
    __shared__ float qs[224][NOPS];

    const int tid = threadIdx.x;
    const int node = blockIdx.x * 224 + tid;
    const int lg = tid / 7;
    const int j  = tid - lg * 7;
    const size_t prow = ((size_t)(node / 7)) * PAD + (node % 7);

    const float* q0 = qpart + prow * NOPS;
    const float* q1 = qpart + (size_t)MP * NOPS + prow * NOPS;
    #pragma unroll
    for (int o = 0; o < NOPS; o++) qs[tid][o] = q0[o] + q1[o];
    __syncthreads();

    float p[NOPS];
    #pragma unroll
    for (int o = 0; o < NOPS; o++) p[o] = bm[o];
    const float dj = rsqrtf(1.f + 0.5f * (float)j);
    for (int i = 0; i <= j; i++) {
        float c = rsqrtf(1.f + 0.5f * (float)i) * dj;
        if (i != j) c *= 0.5f;                 // edge weight 0.5; self loop 1
        #pragma unroll
        for (int o = 0; o < NOPS; o++) p[o] += c * qs[lg*7 + i][o];
    }

    float best = -3.4e38f; int arg = 0;
    #pragma unroll
    for (int o = 0; o < NOPS; o++) {
        float z = p[o] + gop[(size_t)node * NOPS + o];
        if (z > best) { best = z; arg = o; }   // strict > keeps FIRST max (jnp.argmax)
    }
    #pragma unroll
    for (int o = 0; o < NOPS; o++)
        out[(size_t)node * NOPS + o] = (o == arg) ? 1.0f : 0.0f;
}

// ---------------- host: tensormap encoding via driver entry point ----------------
typedef CUresult (*TmapEncodeFn)(CUtensorMap*, CUtensorMapDataType, cuuint32_t, void*,
    const cuuint64_t*, const cuuint64_t*, const cuuint32_t*, const cuuint32_t*,
    CUtensorMapInterleave, CUtensorMapSwizzle, CUtensorMapL2promotion, CUtensorMapFloatOOBfill);

static TmapEncodeFn get_encode_fn()
{
    static TmapEncodeFn fn = nullptr;
    if (!fn) {
        void* p = nullptr;
        cudaDriverEntryPointQueryResult qr;
#if CUDART_VERSION >= 12050
        cudaGetDriverEntryPointByVersion("cuTensorMapEncodeTiled", &p, 12000,
                                         cudaEnableDefault, &qr);
#else
        cudaGetDriverEntryPoint("cuTensorMapEncodeTiled", &p, cudaEnableDefault, &qr);
#endif
        fn = (TmapEncodeFn)p;
    }
    return fn;
}

static void encode_2d(TmapEncodeFn fn, CUtensorMap* m, void* base, unsigned long long rows)
{
    cuuint64_t dims[2]    = {HID, rows};
    cuuint64_t strides[1] = {HID * 2};         // bytes between rows
    cuuint32_t box[2]     = {BK, BM};          // 32 fp16 (64 B) x 128 rows
    cuuint32_t es[2]      = {1, 1};
    fn(m, CU_TENSOR_MAP_DATA_TYPE_FLOAT16, 2, base, dims, strides, box, es,
       CU_TENSOR_MAP_INTERLEAVE_NONE, CU_TENSOR_MAP_SWIZZLE_64B,
       CU_TENSOR_MAP_L2_PROMOTION_L2_128B, CU_TENSOR_MAP_FLOAT_OOB_FILL_NONE);
}

extern "C" void kernel_launch(void* const* d_in, const int* in_sizes, int n_in,
                              void* d_out, int out_size)
{
    const float* x   = (const float*)d_in[0];
    // d_in[1] edge_index, d_in[2] batch: fixed DAG folded into closed-form coefficients
    const float* W1  = (const float*)d_in[3];
    const float* b1  = (const float*)d_in[4];
    const float* W2  = (const float*)d_in[5];
    const float* b2  = (const float*)d_in[6];
    // d_in[7] We, d_in[8] be, d_in[11] g_edge: dead — avg of 2-way softmax == 0.5 exactly
    const float* Wm  = (const float*)d_in[9];
    const float* bm  = (const float*)d_in[10];
    const float* gop = (const float*)d_in[12];
    float* out = (float*)d_out;

    __half *Xsp, *H1sp, *Wsp;
    float* qpart;
    cudaGetSymbolAddress((void**)&Xsp,   g_Xsp);
    cudaGetSymbolAddress((void**)&H1sp,  g_H1sp);
    cudaGetSymbolAddress((void**)&Wsp,   g_Wsp);
    cudaGetSymbolAddress((void**)&qpart, g_qpart);

    TmapEncodeFn fn = get_encode_fn();
    CUtensorMap tX, tH, tW;
    encode_2d(fn, &tX, Xsp,  2ull*MP);   // rows: comp*MP + m
    encode_2d(fn, &tH, H1sp, 2ull*MP);
    encode_2d(fn, &tW, Wsp,  1024ull);   // rows: layer*512 + comp*256 + n

    cudaFuncSetAttribute(gemm_mma, cudaFuncAttributeMaxDynamicSharedMemorySize, SMEM_DYN);

    split_x<<<NGR, 256>>>(x);
    w_prep<<<dim3(HID, 2), HID>>>(W1, W2);

    dim3 grid(HID / BN, MP / BM);        // (2, 1250)
    gemm_mma<<<grid, 256, SMEM_DYN>>>(tX, tW, 0,   b1, H1sp,    nullptr, nullptr, 0);
    gemm_mma<<<grid, 256, SMEM_DYN>>>(tH, tW, 512, b2, nullptr, Wm,      qpart,   1);

    op_select<<<NN / 224, 224>>>(qpart, bm, gop, out);
}

// round 16
// speedup vs baseline: 1.6331x; 1.0501x over previous
#include <cuda_runtime.h>
#include <cuda.h>
#include <cuda_fp16.h>
#include <cstdint>

#define NGR   20000
#define NODES 7
#define PAD   8
#define MP    (NGR*PAD)        // 160000 padded rows
#define NN    (NGR*NODES)      // 140000 real nodes
#define HID   256
#define NOPS  5

#define BM 128                 // 16 graphs (8 padded rows each)
#define BN 128
#define BK 32
#define STAGES (HID/BK)        // 8
#define NBUF 3
#define THREADS 128            // 4 warps, warp tile 64x64

#define PLANE 8192             // one 128-row x 64-byte SW64 tile
#define BUFB  (4*PLANE)        // A0,A1,B0,B1 = 32768 per stage
#define MBAR_OFF (NBUF*BUFB)   // mbarriers after buffers (and after 67584B epilogue staging)
#define SMEM_DYN (NBUF*BUFB + 64 + 1024)   // +1024 manual alignment slack

#define WSCALE     64.0f
#define INV_WSCALE 0.015625f
#define HH  (HID*HID)
#define MPH ((size_t)MP*HID)

// ---------------- device globals (no allocs allowed) ----------------
__device__ __half g_Xsp [(size_t)2*MP*HID];   // fp16x2 planes of padded X
__device__ __half g_H1sp[(size_t)2*MP*HID];   // fp16x2 planes of padded H1
__device__ __half g_Wsp[2][2*HID*HID];        // per-layer fp16x2 of 64*W, [n][k]
__device__ float g_qpart[(size_t)2*MP*NOPS];  // per-N-tile partial H2@Wm

typedef uint32_t u32;

// ---------------- PTX helpers (base sm_90-class features only) ----------------
__device__ __forceinline__ u32 s2u(const void* p){
    u32 a;
    asm("{ .reg .u64 t; cvta.to.shared.u64 t, %1; cvt.u32.u64 %0, t; }" : "=r"(a) : "l"(p));
    return a;
}
#define MBAR_INIT(a,c)  asm volatile("mbarrier.init.shared.b64 [%0], %1;" :: "r"(a), "r"(c) : "memory")
#define MBAR_EXPECT_TX(a, b) \
    asm volatile("mbarrier.arrive.expect_tx.shared.b64 _, [%0], %1;" :: "r"(a), "r"((u32)(b)) : "memory")
#define MBAR_WAIT_PARITY(mbar, parity) do {                                          \
    u32 _m = (mbar); u32 _p = (parity); u32 _done;                                   \
    asm volatile("{\n\t.reg .pred p;\n\t"                                            \
        "mbarrier.try_wait.parity.acquire.cta.shared::cta.b64 p, [%1], %2;\n\t"      \
        "selp.b32 %0, 1, 0, p;\n\t}" : "=r"(_done) : "r"(_m), "r"(_p) : "memory");   \
    if (!_done) {                                                                    \
        asm volatile("{\n\t.reg .pred P1;\n\t"                                       \
            "WL_%=:\n\t"                                                             \
            "mbarrier.try_wait.parity.acquire.cta.shared::cta.b64 P1, [%0], %1, 0x989680;\n\t" \
            "@P1 bra.uni WD_%=;\n\t"                                                 \
            "bra.uni WL_%=;\n\t"                                                     \
            "WD_%=:\n\t}" :: "r"(_m), "r"(_p) : "memory");                           \
    }                                                                                \
} while (0)

#define TMA2D(dst, map_ptr, cx, cy, mbar) \
    asm volatile("cp.async.bulk.tensor.2d.shared::cta.global.tile.mbarrier::complete_tx::bytes " \
        "[%0], [%1, {%2, %3}], [%4];" \
        :: "r"(dst), "l"(map_ptr), "r"((int)(cx)), "r"((int)(cy)), "r"(mbar) : "memory")

__device__ __forceinline__ void ldsm_x4(u32& r0,u32& r1,u32& r2,u32& r3, u32 a){
    asm volatile("ldmatrix.sync.aligned.m8n8.x4.shared.b16 {%0,%1,%2,%3}, [%4];"
                 : "=r"(r0),"=r"(r1),"=r"(r2),"=r"(r3) : "r"(a));
}
__device__ __forceinline__ void mma16816(float* c, const u32* a, const u32* b){
    asm volatile("mma.sync.aligned.m16n8k16.row.col.f32.f16.f16.f32 "
        "{%0,%1,%2,%3}, {%4,%5,%6,%7}, {%8,%9}, {%0,%1,%2,%3};"
        : "+f"(c[0]),"+f"(c[1]),"+f"(c[2]),"+f"(c[3])
        : "r"(a[0]),"r"(a[1]),"r"(a[2]),"r"(a[3]), "r"(b[0]),"r"(b[1]));
}
__device__ __forceinline__ u32 swz64(u32 off){ return off ^ ((off >> 3) & 0x30); }

// fp32 -> 2-way fp16 split of adjacent pair (lo=x, hi=y), packed f16x2
__device__ __forceinline__ void split2h(float x, float y, u32& p0, u32& p1){
    u32 hx = (u32)__half_as_ushort(__float2half_rn(x));
    u32 hy = (u32)__half_as_ushort(__float2half_rn(y));
    p0 = hx | (hy << 16);
    float rx = x - __half2float(__ushort_as_half((unsigned short)hx));
    float ry = y - __half2float(__ushort_as_half((unsigned short)hy));
    u32 gx = (u32)__half_as_ushort(__float2half_rn(rx));
    u32 gy = (u32)__half_as_ushort(__float2half_rn(ry));
    p1 = gx | (gy << 16);
}

// ============ X -> padded fp16x2 planes ============
__global__ __launch_bounds__(256)
void split_x(const float* __restrict__ x)
{
    const int g = blockIdx.x, t = threadIdx.x;
    const int cp = (t & 127) * 2;
    const int rh = t >> 7;
    #pragma unroll
    for (int rr = 0; rr < 4; rr++) {
        int row = rr*2 + rh;
        u32 p0 = 0, p1 = 0;
        if (row < NODES) {
            const float* s = x + ((size_t)g*NODES + row) * HID + cp;
            split2h(s[0], s[1], p0, p1);
        }
        size_t o = ((size_t)g*PAD + row) * HID + cp;
        *(u32*)(g_Xsp + o)        = p0;
        *(u32*)(g_Xsp + MPH + o)  = p1;
    }
}

// ====== fp16x2 3-pass HMMA GEMM, TMA transport, 4 warps x (64x64) warp tiles ======
// mode 0 (layer 1): write H1 as fp16x2 planes.  mode 1 (layer 2): fused Wm -> qpart.
__global__ __launch_bounds__(THREADS, 2)
void gemm_mma(const __grid_constant__ CUtensorMap tA,
              const __grid_constant__ CUtensorMap tB, int nbase,
              const float* __restrict__ bias, __half* __restrict__ Hsp,
              const float* __restrict__ WmG, float* __restrict__ qpart, int mode)
{
    extern __shared__ __align__(128) char smem[];
    const u32 sb_raw = s2u(smem);
    const u32 sb = (sb_raw + 1023u) & ~1023u;      // 1KB-align: TMA dst + SW64 atom base
    char* smemA = smem + (sb - sb_raw);            // aligned alias for epilogue staging
    const u32 mb = sb + MBAR_OFF;                  // mbarriers live in dynamic smem

    const int tid  = threadIdx.x;
    const int lane = tid & 31;
    const int warp = tid >> 5;         // 0..3
    const int wm = warp >> 1;          // 0..1  (M: 64-row slab)
    const int wn = warp & 1;           // 0..1  (N: 64-col slab)
    const int m0 = blockIdx.y * BM;
    const int n0 = blockIdx.x * BN;

    const void* pA = (const void*)&tA;
    const void* pB = (const void*)&tB;

    if (tid == 0) {
        #pragma unroll
        for (int b = 0; b < NBUF; b++) MBAR_INIT(mb + b*8, 1);
    }
    __syncthreads();

    #define ISSUE(s_) do {                                                   \
        u32 bb_ = sb + (u32)((s_) % NBUF) * BUFB;                            \
        u32 mb_ = mb + ((s_) % NBUF) * 8;                                    \
        MBAR_EXPECT_TX(mb_, BUFB);                                           \
        TMA2D(bb_,             pA, (s_)*BK, m0,               mb_);          \
        TMA2D(bb_ + PLANE,     pA, (s_)*BK, MP + m0,          mb_);          \
        TMA2D(bb_ + 2*PLANE,   pB, (s_)*BK, nbase + n0,       mb_);          \
        TMA2D(bb_ + 3*PLANE,   pB, (s_)*BK, nbase + 256 + n0, mb_);          \
    } while(0)

    if (tid == 0) { ISSUE(0); ISSUE(1); ISSUE(2); }

    float acc[128];
    #pragma unroll
    for (int i = 0; i < 128; i++) acc[i] = 0.f;

    // ldmatrix lane addressing (SW64 swizzled 64B rows)
    const u32 a_base = (u32)((wm*64 + (lane & 15)) * 64 + (lane >> 4) * 16);
    // B paired-x4: lanes 0-7 (nt0 k0-7), 8-15 (nt0 k8-15), 16-23 (nt1 k0-7), 24-31 (nt1 k8-15)
    const u32 b_base = (u32)((wn*64 + (lane & 7) + ((lane >> 4) << 3)) * 64 + ((lane >> 3) & 1) * 16);

    #pragma unroll 1
    for (int s = 0; s < STAGES; s++) {
        MBAR_WAIT_PARITY(mb + (s % NBUF)*8, (u32)((s / NBUF) & 1));
        const u32 bb = sb + (u32)(s % NBUF) * BUFB;

        #pragma unroll
        for (int kh = 0; kh < 2; kh++) {
            u32 afr[4][2][4];              // 4 m-tiles x 2 splits
            #pragma unroll
            for (int mt = 0; mt < 4; mt++)
                #pragma unroll
                for (int sp = 0; sp < 2; sp++)
                    ldsm_x4(afr[mt][sp][0], afr[mt][sp][1], afr[mt][sp][2], afr[mt][sp][3],
                            bb + sp*PLANE + swz64(a_base + mt*16*64 + kh*32));

            #pragma unroll
            for (int ntp = 0; ntp < 4; ntp++) {
                u32 bfr[2][2][2];          // [h][split][2 regs]
                #pragma unroll
                for (int sp = 0; sp < 2; sp++)
                    ldsm_x4(bfr[0][sp][0], bfr[0][sp][1], bfr[1][sp][0], bfr[1][sp][1],
                            bb + (2 + sp)*PLANE + swz64(b_base + ntp*16*64 + kh*32));

                // pass 1: a0*b0
                #pragma unroll
                for (int h = 0; h < 2; h++)
                    #pragma unroll
                    for (int mt = 0; mt < 4; mt++)
                        mma16816(&acc[(mt*8 + 2*ntp + h)*4], afr[mt][0], bfr[h][0]);
                // pass 2: a0*b1
                #pragma unroll
                for (int h = 0; h < 2; h++)
                    #pragma unroll
                    for (int mt = 0; mt < 4; mt++)
                        mma16816(&acc[(mt*8 + 2*ntp + h)*4], afr[mt][0], bfr[h][1]);
                // pass 3: a1*b0
                #pragma unroll
                for (int h = 0; h < 2; h++)
                    #pragma unroll
                    for (int mt = 0; mt < 4; mt++)
                        mma16816(&acc[(mt*8 + 2*ntp + h)*4], afr[mt][1], bfr[h][0]);
            }
        }

        __syncthreads();                       // all warps done with buffer s%NBUF
        if (tid == 0 && s + NBUF < STAGES) ISSUE(s + NBUF);
    }
    #undef ISSUE

    // ---- epilogue: accs -> smem, GCN agg (x1/64) + bias + relu
    float* Ds = (float*)smemA;                 // [128][132], aligned base
    {
        const int r0 = wm*64 + (lane >> 2);
        const int c0 = wn*64 + (lane & 3)*2;
        #pragma unroll
        for (int mt = 0; mt < 4; mt++)
            #pragma unroll
            for (int nt = 0; nt < 8; nt++) {
                const float* c = &acc[(mt*8 + nt)*4];
                float* d = &Ds[(size_t)(r0 + mt*16)*132 + c0 + nt*8];
                d[0] = c[0]; d[1] = c[1];
                d[132*8 + 0] = c[2]; d[132*8 + 1] = c[3];
            }
    }
    __syncthreads();

    {
        const int cg = tid & 15;               // 8-col group (16)
        float dinv[7];
        #pragma unroll
        for (int j = 0; j < 7; j++) dinv[j] = rsqrtf((float)(j + 1));
        float bv[8];
        #pragma unroll
        for (int c = 0; c < 8; c++) bv[c] = bias[n0 + cg*8 + c];

        float wreg[40];
        if (mode == 1) {
            #pragma unroll
            for (int c = 0; c < 8; c++)
                #pragma unroll
                for (int o = 0; o < NOPS; o++)
                    wreg[c*NOPS + o] = __ldg(&WmG[(size_t)(n0 + cg*8 + c)*NOPS + o]);
        }

        #pragma unroll 1
        for (int gh = 0; gh < 2; gh++) {       // two 8-graph halves (128 threads)
            const int g = gh*8 + (tid >> 4);   // graph in tile
            float gv[7][8];
            #pragma unroll
            for (int i = 0; i < 7; i++) {
                float4 lo = *(float4*)&Ds[(size_t)(g*8 + i)*132 + cg*8];
                float4 hi = *(float4*)&Ds[(size_t)(g*8 + i)*132 + cg*8 + 4];
                gv[i][0]=lo.x; gv[i][1]=lo.y; gv[i][2]=lo.z; gv[i][3]=lo.w;
                gv[i][4]=hi.x; gv[i][5]=hi.y; gv[i][6]=hi.z; gv[i][7]=hi.w;
            }

            if (mode == 0) {
                // ---- layer 1: write fp16x2 planes of padded H1
                #pragma unroll
                for (int j = 0; j < 7; j++) {
                    float v[8];
                    #pragma unroll
                    for (int c = 0; c < 8; c++) v[c] = 0.f;
                    #pragma unroll
                    for (int i = 0; i < 7; i++) {
                        if (i <= j) {
                            float cji = dinv[i] * dinv[j] * INV_WSCALE;
                            #pragma unroll
                            for (int c = 0; c < 8; c++) v[c] = fmaf(cji, gv[i][c], v[c]);
                        }
                    }
                    #pragma unroll
                    for (int c = 0; c < 8; c++) v[c] = fmaxf(v[c] + bv[c], 0.f);

                    u32 p0[4], p1[4];
                    split2h(v[0], v[1], p0[0], p1[0]);
                    split2h(v[2], v[3], p0[1], p1[1]);
                    split2h(v[4], v[5], p0[2], p1[2]);
                    split2h(v[6], v[7], p0[3], p1[3]);
                    const size_t ob = (size_t)(m0 + g*8 + j) * HID + n0 + cg*8;
                    *(uint4*)(Hsp + ob)       = make_uint4(p0[0], p0[1], p0[2], p0[3]);
                    *(uint4*)(Hsp + MPH + ob) = make_uint4(p1[0], p1[1], p1[2], p1[3]);
                }
                {   // pad row 7 must be zero for layer-2 TMA loads
                    const size_t ob = (size_t)(m0 + g*8 + 7) * HID + n0 + cg*8;
                    uint4 z = make_uint4(0,0,0,0);
                    *(uint4*)(Hsp + ob)       = z;
                    *(uint4*)(Hsp + MPH + ob) = z;
                }
            } else {
                // ---- layer 2: fused Wm projection -> qpart
                float pq[7*NOPS];
                #pragma unroll
                for (int t = 0; t < 7*NOPS; t++) pq[t] = 0.f;

                #pragma unroll
                for (int j = 0; j < 7; j++) {
                    float v[8];
                    #pragma unroll
                    for (int c = 0; c < 8; c++) v[c] = 0.f;
                    #pragma unroll
                    for (int i = 0; i < 7; i++) {
                        if (i <= j) {
                            float cji = dinv[i] * dinv[j] * INV_WSCALE;
                            #pragma unroll
                            for (int c = 0; c < 8; c++) v[c] = fmaf(cji, gv[i][c], v[c]);
                        }
                    }
                    #pragma unroll
                    for (int c = 0; c < 8; c++) {
                        float vv = fmaxf(v[c] + bv[c], 0.f);
                        #pragma unroll
                        for (int o = 0; o < NOPS; o++)
                            pq[j*NOPS + o] = fmaf(vv, wreg[c*NOPS + o], pq[j*NOPS + o]);
                    }
                }

                // reduce over the 16 cg-lanes (xor 8,4,2,1 stays inside 16-lane half)
                #pragma unroll
                for (int t = 0; t < 7*NOPS; t++) {
                    #pragma unroll
                    for (int off = 8; off; off >>= 1)
                        pq[t] += __shfl_xor_sync(0xFFFFFFFFu, pq[t], off);
                }
                if (cg == 0) {
                    float* qp = qpart + (size_t)blockIdx.x * MP * NOPS
                                      + (size_t)(m0 + g*8) * NOPS;
                    #pragma unroll
                    for (int t = 0; t < 7*NOPS; t++) qp[t] = pq[t];
                }
            }
        }
    }
}

// ============ W -> fp16x2 split of 64*W, transposed to [n][k] ====================
__global__ void w_prep(const float* __restrict__ W1, const float* __restrict__ W2)
{
    const int layer = blockIdx.y;
    const float* W = layer ? W2 : W1;
    __half* O = g_Wsp[layer];
    const int k = blockIdx.x;
    const int n = threadIdx.x;
    float w = W[(size_t)k * HID + n] * WSCALE;
    __half c0 = __float2half_rn(w);
    float r = w - __half2float(c0);
    __half c1 = __float2half_rn(r);
    size_t o = (size_t)n * HID + k;
    O[o]      = c0;
    O[HH + o] = c1;
}

// ============ final: combine q partials, weighted agg, hard argmax ============
__global__ __launch_bounds__(224)
void op_select(const float* __restrict__ qpart, const float* __restrict__ bm,
               const float* __restrict__ gop, float* __restrict__ out)
{
    __shared__ float qs[224][NOPS];

    const int tid = threadIdx.x;
    const int node = blockIdx.x * 224 + tid;
    const int lg = tid / 7;
    const int j  = tid - lg * 7;
    const size_t prow = ((size_t)(node / 7)) * PAD + (node % 7);

    const float* q0 = qpart + prow * NOPS;
    const float* q1 = qpart + (size_t)MP * NOPS + prow * NOPS;
    #pragma unroll
    for (int o = 0; o < NOPS; o++) qs[tid][o] = q0[o] + q1[o];
    __syncthreads();

    float p[NOPS];
    #pragma unroll
    for (int o = 0; o < NOPS; o++) p[o] = bm[o];
    const float dj = rsqrtf(1.f + 0.5f * (float)j);
    for (int i = 0; i <= j; i++) {
        float c = rsqrtf(1.f + 0.5f * (float)i) * dj;
        if (i != j) c *= 0.5f;                 // edge weight 0.5; self loop 1
        #pragma unroll
        for (int o = 0; o < NOPS; o++) p[o] += c * qs[lg*7 + i][o];
    }

    float best = -3.4e38f; int arg = 0;
    #pragma unroll
    for (int o = 0; o < NOPS; o++) {
        float z = p[o] + gop[(size_t)node * NOPS + o];
        if (z > best) { best = z; arg = o; }   // strict > keeps FIRST max (jnp.argmax)
    }
    #pragma unroll
    for (int o = 0; o < NOPS; o++)
        out[(size_t)node * NOPS + o] = (o == arg) ? 1.0f : 0.0f;
}

// ---------------- host: tensormap encoding via driver entry point ----------------
typedef CUresult (*TmapEncodeFn)(CUtensorMap*, CUtensorMapDataType, cuuint32_t, void*,
    const cuuint64_t*, const cuuint64_t*, const cuuint32_t*, const cuuint32_t*,
    CUtensorMapInterleave, CUtensorMapSwizzle, CUtensorMapL2promotion, CUtensorMapFloatOOBfill);

static TmapEncodeFn get_encode_fn()
{
    static TmapEncodeFn fn = nullptr;
    if (!fn) {
        void* p = nullptr;
        cudaDriverEntryPointQueryResult qr;
#if CUDART_VERSION >= 12050
        cudaGetDriverEntryPointByVersion("cuTensorMapEncodeTiled", &p, 12000,
                                         cudaEnableDefault, &qr);
#else
        cudaGetDriverEntryPoint("cuTensorMapEncodeTiled", &p, cudaEnableDefault, &qr);
#endif
        fn = (TmapEncodeFn)p;
    }
    return fn;
}

static void encode_2d(TmapEncodeFn fn, CUtensorMap* m, void* base, unsigned long long rows)
{
    cuuint64_t dims[2]    = {HID, rows};
    cuuint64_t strides[1] = {HID * 2};         // bytes between rows
    cuuint32_t box[2]     = {BK, BM};          // 32 fp16 (64 B) x 128 rows
    cuuint32_t es[2]      = {1, 1};
    fn(m, CU_TENSOR_MAP_DATA_TYPE_FLOAT16, 2, base, dims, strides, box, es,
       CU_TENSOR_MAP_INTERLEAVE_NONE, CU_TENSOR_MAP_SWIZZLE_64B,
       CU_TENSOR_MAP_L2_PROMOTION_L2_128B, CU_TENSOR_MAP_FLOAT_OOB_FILL_NONE);
}

extern "C" void kernel_launch(void* const* d_in, const int* in_sizes, int n_in,
                              void* d_out, int out_size)
{
    const float* x   = (const float*)d_in[0];
    // d_in[1] edge_index, d_in[2] batch: fixed DAG folded into closed-form coefficients
    const float* W1  = (const float*)d_in[3];
    const float* b1  = (const float*)d_in[4];
    const float* W2  = (const float*)d_in[5];
    const float* b2  = (const float*)d_in[6];
    // d_in[7] We, d_in[8] be, d_in[11] g_edge: dead — avg of 2-way softmax == 0.5 exactly
    const float* Wm  = (const float*)d_in[9];
    const float* bm  = (const float*)d_in[10];
    const float* gop = (const float*)d_in[12];
    float* out = (float*)d_out;

    __half *Xsp, *H1sp, *Wsp;
    float* qpart;
    cudaGetSymbolAddress((void**)&Xsp,   g_Xsp);
    cudaGetSymbolAddress((void**)&H1sp,  g_H1sp);
    cudaGetSymbolAddress((void**)&Wsp,   g_Wsp);
    cudaGetSymbolAddress((void**)&qpart, g_qpart);

    TmapEncodeFn fn = get_encode_fn();
    CUtensorMap tX, tH, tW;
    encode_2d(fn, &tX, Xsp,  2ull*MP);   // rows: comp*MP + m
    encode_2d(fn, &tH, H1sp, 2ull*MP);
    encode_2d(fn, &tW, Wsp,  1024ull);   // rows: layer*512 + comp*256 + n

    cudaFuncSetAttribute(gemm_mma, cudaFuncAttributeMaxDynamicSharedMemorySize, SMEM_DYN);

    split_x<<<NGR, 256>>>(x);
    w_prep<<<dim3(HID, 2), HID>>>(W1, W2);

    dim3 grid(HID / BN, MP / BM);        // (2, 1250)
    gemm_mma<<<grid, THREADS, SMEM_DYN>>>(tX, tW, 0,   b1, H1sp,    nullptr, nullptr, 0);
    gemm_mma<<<grid, THREADS, SMEM_DYN>>>(tH, tW, 512, b2, nullptr, Wm,      qpart,   1);

    op_select<<<NN / 224, 224>>>(qpart, bm, gop, out);
}

// round 17
// speedup vs baseline: 1.6654x; 1.0198x over previous
#include <cuda_runtime.h>
#include <cuda.h>
#include <cuda_fp16.h>
#include <cstdint>

#define NGR   20000
#define NODES 7
#define PAD   8
#define MP    (NGR*PAD)        // 160000 padded rows
#define NN    (NGR*NODES)      // 140000 real nodes
#define HID   256
#define NOPS  5

#define BM 128                 // 16 graphs (8 padded rows each)
#define BN 128
#define BK 32
#define STAGES (HID/BK)        // 8
#define NBUF 3
#define THREADS 128            // 4 warps, warp tile 64x64

#define PLANE 8192             // one 128-row x 64-byte SW64 tile
#define BUFB  (4*PLANE)        // A0,A1,B0,B1 = 32768 per stage
#define MBAR_OFF (NBUF*BUFB)   // full[0..2] then empty[0..2]
#define SMEM_DYN (NBUF*BUFB + 64 + 1024)   // +1024 manual alignment slack

#define WSCALE     64.0f
#define INV_WSCALE 0.015625f
#define HH  (HID*HID)
#define MPH ((size_t)MP*HID)

// ---------------- device globals (no allocs allowed) ----------------
__device__ __half g_Xsp [(size_t)2*MP*HID];   // fp16x2 planes of padded X
__device__ __half g_H1sp[(size_t)2*MP*HID];   // fp16x2 planes of padded H1
__device__ __half g_Wsp[2][2*HID*HID];        // per-layer fp16x2 of 64*W, [n][k]
__device__ float g_qpart[(size_t)2*MP*NOPS];  // per-N-tile partial H2@Wm

typedef uint32_t u32;

// ---------------- PTX helpers (base sm_90-class features only) ----------------
__device__ __forceinline__ u32 s2u(const void* p){
    u32 a;
    asm("{ .reg .u64 t; cvta.to.shared.u64 t, %1; cvt.u32.u64 %0, t; }" : "=r"(a) : "l"(p));
    return a;
}
#define MBAR_INIT(a,c)  asm volatile("mbarrier.init.shared.b64 [%0], %1;" :: "r"(a), "r"(c) : "memory")
#define MBAR_ARRIVE(a)  asm volatile("mbarrier.arrive.shared.b64 _, [%0];" :: "r"(a) : "memory")
#define MBAR_EXPECT_TX(a, b) \
    asm volatile("mbarrier.arrive.expect_tx.shared.b64 _, [%0], %1;" :: "r"(a), "r"((u32)(b)) : "memory")
#define MBAR_WAIT_PARITY(mbar, parity) do {                                          \
    u32 _m = (mbar); u32 _p = (parity); u32 _done;                                   \
    asm volatile("{\n\t.reg .pred p;\n\t"                                            \
        "mbarrier.try_wait.parity.acquire.cta.shared::cta.b64 p, [%1], %2;\n\t"      \
        "selp.b32 %0, 1, 0, p;\n\t}" : "=r"(_done) : "r"(_m), "r"(_p) : "memory");   \
    if (!_done) {                                                                    \
        asm volatile("{\n\t.reg .pred P1;\n\t"                                       \
            "WL_%=:\n\t"                                                             \
            "mbarrier.try_wait.parity.acquire.cta.shared::cta.b64 P1, [%0], %1, 0x989680;\n\t" \
            "@P1 bra.uni WD_%=;\n\t"                                                 \
            "bra.uni WL_%=;\n\t"                                                     \
            "WD_%=:\n\t}" :: "r"(_m), "r"(_p) : "memory");                           \
    }                                                                                \
} while (0)

#define TMA2D(dst, map_ptr, cx, cy, mbar) \
    asm volatile("cp.async.bulk.tensor.2d.shared::cta.global.tile.mbarrier::complete_tx::bytes " \
        "[%0], [%1, {%2, %3}], [%4];" \
        :: "r"(dst), "l"(map_ptr), "r"((int)(cx)), "r"((int)(cy)), "r"(mbar) : "memory")

__device__ __forceinline__ void ldsm_x4(u32& r0,u32& r1,u32& r2,u32& r3, u32 a){
    asm volatile("ldmatrix.sync.aligned.m8n8.x4.shared.b16 {%0,%1,%2,%3}, [%4];"
                 : "=r"(r0),"=r"(r1),"=r"(r2),"=r"(r3) : "r"(a));
}
__device__ __forceinline__ void mma16816(float* c, const u32* a, const u32* b){
    asm volatile("mma.sync.aligned.m16n8k16.row.col.f32.f16.f16.f32 "
        "{%0,%1,%2,%3}, {%4,%5,%6,%7}, {%8,%9}, {%0,%1,%2,%3};"
        : "+f"(c[0]),"+f"(c[1]),"+f"(c[2]),"+f"(c[3])
        : "r"(a[0]),"r"(a[1]),"r"(a[2]),"r"(a[3]), "r"(b[0]),"r"(b[1]));
}
__device__ __forceinline__ u32 swz64(u32 off){ return off ^ ((off >> 3) & 0x30); }

// fp32 -> 2-way fp16 split of adjacent pair (lo=x, hi=y), packed f16x2
__device__ __forceinline__ void split2h(float x, float y, u32& p0, u32& p1){
    u32 hx = (u32)__half_as_ushort(__float2half_rn(x));
    u32 hy = (u32)__half_as_ushort(__float2half_rn(y));
    p0 = hx | (hy << 16);
    float rx = x - __half2float(__ushort_as_half((unsigned short)hx));
    float ry = y - __half2float(__ushort_as_half((unsigned short)hy));
    u32 gx = (u32)__half_as_ushort(__float2half_rn(rx));
    u32 gy = (u32)__half_as_ushort(__float2half_rn(ry));
    p1 = gx | (gy << 16);
}

// ============ X -> padded fp16x2 planes, plus W -> fp16x2 split (merged) ============
__global__ __launch_bounds__(256)
void prep_all(const float* __restrict__ x,
              const float* __restrict__ W1, const float* __restrict__ W2)
{
    const int b = blockIdx.x, t = threadIdx.x;
    if (b < NGR) {
        const int cp = (t & 127) * 2;
        const int rh = t >> 7;
        #pragma unroll
        for (int rr = 0; rr < 4; rr++) {
            int row = rr*2 + rh;
            u32 p0 = 0, p1 = 0;
            if (row < NODES) {
                const float* s = x + ((size_t)b*NODES + row) * HID + cp;
                split2h(s[0], s[1], p0, p1);
            }
            size_t o = ((size_t)b*PAD + row) * HID + cp;
            *(u32*)(g_Xsp + o)        = p0;
            *(u32*)(g_Xsp + MPH + o)  = p1;
        }
    } else {
        const int idx = b - NGR;            // 0..511
        const int layer = idx >> 8;
        const int k = idx & 255;
        const float* W = layer ? W2 : W1;
        __half* O = g_Wsp[layer];
        float w = W[(size_t)k * HID + t] * WSCALE;
        __half c0 = __float2half_rn(w);
        float r = w - __half2float(c0);
        __half c1 = __float2half_rn(r);
        size_t o = (size_t)t * HID + k;
        O[o]      = c0;
        O[HH + o] = c1;
    }
}

// ====== fp16x2 3-pass HMMA GEMM, TMA + producer/consumer mbarriers, 64x64 warp tiles ======
// mode 0 (layer 1): write H1 as fp16x2 planes.  mode 1 (layer 2): fused Wm -> qpart.
__global__ __launch_bounds__(THREADS, 2)
void gemm_mma(const __grid_constant__ CUtensorMap tA,
              const __grid_constant__ CUtensorMap tB, int nbase,
              const float* __restrict__ bias, __half* __restrict__ Hsp,
              const float* __restrict__ WmG, float* __restrict__ qpart, int mode)
{
    extern __shared__ __align__(128) char smem[];
    const u32 sb_raw = s2u(smem);
    const u32 sb = (sb_raw + 1023u) & ~1023u;      // 1KB-align: TMA dst + SW64 atom base
    char* smemA = smem + (sb - sb_raw);            // aligned alias for epilogue staging
    const u32 mbF = sb + MBAR_OFF;                 // full barriers
    const u32 mbE = sb + MBAR_OFF + 24;            // empty barriers

    const int tid  = threadIdx.x;
    const int lane = tid & 31;
    const int warp = tid >> 5;         // 0..3
    const int wm = warp >> 1;          // 0..1  (M: 64-row slab)
    const int wn = warp & 1;           // 0..1  (N: 64-col slab)
    const int m0 = blockIdx.y * BM;
    const int n0 = blockIdx.x * BN;

    const void* pA = (const void*)&tA;
    const void* pB = (const void*)&tB;

    if (tid == 0) {
        #pragma unroll
        for (int b = 0; b < NBUF; b++) { MBAR_INIT(mbF + b*8, 1); MBAR_INIT(mbE + b*8, THREADS); }
    }
    __syncthreads();

    #define ISSUE(s_) do {                                                   \
        u32 bb_ = sb + (u32)((s_) % NBUF) * BUFB;                            \
        u32 mb_ = mbF + ((s_) % NBUF) * 8;                                   \
        MBAR_EXPECT_TX(mb_, BUFB);                                           \
        TMA2D(bb_,             pA, (s_)*BK, m0,               mb_);          \
        TMA2D(bb_ + PLANE,     pA, (s_)*BK, MP + m0,          mb_);          \
        TMA2D(bb_ + 2*PLANE,   pB, (s_)*BK, nbase + n0,       mb_);          \
        TMA2D(bb_ + 3*PLANE,   pB, (s_)*BK, nbase + 256 + n0, mb_);          \
    } while(0)

    if (tid == 0) { ISSUE(0); ISSUE(1); ISSUE(2); }

    float acc[128];
    #pragma unroll
    for (int i = 0; i < 128; i++) acc[i] = 0.f;

    // ldmatrix lane addressing (SW64 swizzled 64B rows)
    const u32 a_base = (u32)((wm*64 + (lane & 15)) * 64 + (lane >> 4) * 16);
    // B paired-x4: lanes 0-7 (nt0 k0-7), 8-15 (nt0 k8-15), 16-23 (nt1 k0-7), 24-31 (nt1 k8-15)
    const u32 b_base = (u32)((wn*64 + (lane & 7) + ((lane >> 4) << 3)) * 64 + ((lane >> 3) & 1) * 16);

    #pragma unroll 1
    for (int s = 0; s < STAGES; s++) {
        MBAR_WAIT_PARITY(mbF + (s % NBUF)*8, (u32)((s / NBUF) & 1));
        const u32 bb = sb + (u32)(s % NBUF) * BUFB;

        // preload A fragments for BOTH kh halves (no mid-stage A drain)
        u32 afr[2][4][2][4];               // [kh][mt][split][4]
        #pragma unroll
        for (int kh = 0; kh < 2; kh++)
            #pragma unroll
            for (int mt = 0; mt < 4; mt++)
                #pragma unroll
                for (int sp = 0; sp < 2; sp++)
                    ldsm_x4(afr[kh][mt][sp][0], afr[kh][mt][sp][1],
                            afr[kh][mt][sp][2], afr[kh][mt][sp][3],
                            bb + sp*PLANE + swz64(a_base + mt*16*64 + kh*32));

        #pragma unroll
        for (int kh = 0; kh < 2; kh++) {
            #pragma unroll
            for (int ntp = 0; ntp < 4; ntp++) {
                u32 bfr[2][2][2];          // [h][split][2 regs]
                #pragma unroll
                for (int sp = 0; sp < 2; sp++)
                    ldsm_x4(bfr[0][sp][0], bfr[0][sp][1], bfr[1][sp][0], bfr[1][sp][1],
                            bb + (2 + sp)*PLANE + swz64(b_base + ntp*16*64 + kh*32));

                // pass 1: a0*b0
                #pragma unroll
                for (int h = 0; h < 2; h++)
                    #pragma unroll
                    for (int mt = 0; mt < 4; mt++)
                        mma16816(&acc[(mt*8 + 2*ntp + h)*4], afr[kh][mt][0], bfr[h][0]);
                // pass 2: a0*b1
                #pragma unroll
                for (int h = 0; h < 2; h++)
                    #pragma unroll
                    for (int mt = 0; mt < 4; mt++)
                        mma16816(&acc[(mt*8 + 2*ntp + h)*4], afr[kh][mt][0], bfr[h][1]);
                // pass 3: a1*b0
                #pragma unroll
                for (int h = 0; h < 2; h++)
                    #pragma unroll
                    for (int mt = 0; mt < 4; mt++)
                        mma16816(&acc[(mt*8 + 2*ntp + h)*4], afr[kh][mt][1], bfr[h][0]);
            }
        }

        // signal buffer consumption (no block-wide barrier: warps run ahead)
        MBAR_ARRIVE(mbE + (s % NBUF)*8);
        if (tid == 0 && s + NBUF < STAGES) {
            MBAR_WAIT_PARITY(mbE + (s % NBUF)*8, (u32)((s / NBUF) & 1));
            ISSUE(s + NBUF);
        }
    }
    #undef ISSUE
    __syncthreads();                       // all warps done before Ds overwrites buffers

    // ---- epilogue: accs -> smem, GCN agg (x1/64) + bias + relu
    float* Ds = (float*)smemA;                 // [128][132], aligned base
    {
        const int r0 = wm*64 + (lane >> 2);
        const int c0 = wn*64 + (lane & 3)*2;
        #pragma unroll
        for (int mt = 0; mt < 4; mt++)
            #pragma unroll
            for (int nt = 0; nt < 8; nt++) {
                const float* c = &acc[(mt*8 + nt)*4];
                float* d = &Ds[(size_t)(r0 + mt*16)*132 + c0 + nt*8];
                d[0] = c[0]; d[1] = c[1];
                d[132*8 + 0] = c[2]; d[132*8 + 1] = c[3];
            }
    }
    __syncthreads();

    {
        const int cg = tid & 15;               // 8-col group (16)
        float dinv[7];
        #pragma unroll
        for (int j = 0; j < 7; j++) dinv[j] = rsqrtf((float)(j + 1));
        float bv[8];
        #pragma unroll
        for (int c = 0; c < 8; c++) bv[c] = bias[n0 + cg*8 + c];

        float wreg[40];
        if (mode == 1) {
            #pragma unroll
            for (int c = 0; c < 8; c++)
                #pragma unroll
                for (int o = 0; o < NOPS; o++)
                    wreg[c*NOPS + o] = __ldg(&WmG[(size_t)(n0 + cg*8 + c)*NOPS + o]);
        }

        #pragma unroll 1
        for (int gh = 0; gh < 2; gh++) {       // two 8-graph halves (128 threads)
            const int g = gh*8 + (tid >> 4);   // graph in tile
            float gv[7][8];
            #pragma unroll
            for (int i = 0; i < 7; i++) {
                float4 lo = *(float4*)&Ds[(size_t)(g*8 + i)*132 + cg*8];
                float4 hi = *(float4*)&Ds[(size_t)(g*8 + i)*132 + cg*8 + 4];
                gv[i][0]=lo.x; gv[i][1]=lo.y; gv[i][2]=lo.z; gv[i][3]=lo.w;
                gv[i][4]=hi.x; gv[i][5]=hi.y; gv[i][6]=hi.z; gv[i][7]=hi.w;
            }

            if (mode == 0) {
                // ---- layer 1: write fp16x2 planes of padded H1
                #pragma unroll
                for (int j = 0; j < 7; j++) {
                    float v[8];
                    #pragma unroll
                    for (int c = 0; c < 8; c++) v[c] = 0.f;
                    #pragma unroll
                    for (int i = 0; i < 7; i++) {
                        if (i <= j) {
                            float cji = dinv[i] * dinv[j] * INV_WSCALE;
                            #pragma unroll
                            for (int c = 0; c < 8; c++) v[c] = fmaf(cji, gv[i][c], v[c]);
                        }
                    }
                    #pragma unroll
                    for (int c = 0; c < 8; c++) v[c] = fmaxf(v[c] + bv[c], 0.f);

                    u32 p0[4], p1[4];
                    split2h(v[0], v[1], p0[0], p1[0]);
                    split2h(v[2], v[3], p0[1], p1[1]);
                    split2h(v[4], v[5], p0[2], p1[2]);
                    split2h(v[6], v[7], p0[3], p1[3]);
                    const size_t ob = (size_t)(m0 + g*8 + j) * HID + n0 + cg*8;
                    *(uint4*)(Hsp + ob)       = make_uint4(p0[0], p0[1], p0[2], p0[3]);
                    *(uint4*)(Hsp + MPH + ob) = make_uint4(p1[0], p1[1], p1[2], p1[3]);
                }
                {   // pad row 7 must be zero for layer-2 TMA loads
                    const size_t ob = (size_t)(m0 + g*8 + 7) * HID + n0 + cg*8;
                    uint4 z = make_uint4(0,0,0,0);
                    *(uint4*)(Hsp + ob)       = z;
                    *(uint4*)(Hsp + MPH + ob) = z;
                }
            } else {
                // ---- layer 2: fused Wm projection -> qpart
                float pq[7*NOPS];
                #pragma unroll
                for (int t = 0; t < 7*NOPS; t++) pq[t] = 0.f;

                #pragma unroll
                for (int j = 0; j < 7; j++) {
                    float v[8];
                    #pragma unroll
                    for (int c = 0; c < 8; c++) v[c] = 0.f;
                    #pragma unroll
                    for (int i = 0; i < 7; i++) {
                        if (i <= j) {
                            float cji = dinv[i] * dinv[j] * INV_WSCALE;
                            #pragma unroll
                            for (int c = 0; c < 8; c++) v[c] = fmaf(cji, gv[i][c], v[c]);
                        }
                    }
                    #pragma unroll
                    for (int c = 0; c < 8; c++) {
                        float vv = fmaxf(v[c] + bv[c], 0.f);
                        #pragma unroll
                        for (int o = 0; o < NOPS; o++)
                            pq[j*NOPS + o] = fmaf(vv, wreg[c*NOPS + o], pq[j*NOPS + o]);
                    }
                }

                // reduce over the 16 cg-lanes (xor 8,4,2,1 stays inside 16-lane half)
                #pragma unroll
                for (int t = 0; t < 7*NOPS; t++) {
                    #pragma unroll
                    for (int off = 8; off; off >>= 1)
                        pq[t] += __shfl_xor_sync(0xFFFFFFFFu, pq[t], off);
                }
                if (cg == 0) {
                    float* qp = qpart + (size_t)blockIdx.x * MP * NOPS
                                      + (size_t)(m0 + g*8) * NOPS;
                    #pragma unroll
                    for (int t = 0; t < 7*NOPS; t++) qp[t] = pq[t];
                }
            }
        }
    }
}

// ============ final: combine q partials, weighted agg, hard argmax ============
__global__ __launch_bounds__(224)
void op_select(const float* __restrict__ qpart, const float* __restrict__ bm,
               const float* __restrict__ gop, float* __restrict__ out)
{
    __shared__ float qs[224][NOPS];

    const int tid = threadIdx.x;
    const int node = blockIdx.x * 224 + tid;
    const int lg = tid / 7;
    const int j  = tid - lg * 7;
    const size_t prow = ((size_t)(node / 7)) * PAD + (node % 7);

    const float* q0 = qpart + prow * NOPS;
    const float* q1 = qpart + (size_t)MP * NOPS + prow * NOPS;
    #pragma unroll
    for (int o = 0; o < NOPS; o++) qs[tid][o] = q0[o] + q1[o];
    __syncthreads();

    float p[NOPS];
    #pragma unroll
    for (int o = 0; o < NOPS; o++) p[o] = bm[o];
    const float dj = rsqrtf(1.f + 0.5f * (float)j);
    for (int i = 0; i <= j; i++) {
        float c = rsqrtf(1.f + 0.5f * (float)i) * dj;
        if (i != j) c *= 0.5f;                 // edge weight 0.5; self loop 1
        #pragma unroll
        for (int o = 0; o < NOPS; o++) p[o] += c * qs[lg*7 + i][o];
    }

    float best = -3.4e38f; int arg = 0;
    #pragma unroll
    for (int o = 0; o < NOPS; o++) {
        float z = p[o] + gop[(size_t)node * NOPS + o];
        if (z > best) { best = z; arg = o; }   // strict > keeps FIRST max (jnp.argmax)
    }
    #pragma unroll
    for (int o = 0; o < NOPS; o++)
        out[(size_t)node * NOPS + o] = (o == arg) ? 1.0f : 0.0f;
}

// ---------------- host: tensormap encoding via driver entry point ----------------
typedef CUresult (*TmapEncodeFn)(CUtensorMap*, CUtensorMapDataType, cuuint32_t, void*,
    const cuuint64_t*, const cuuint64_t*, const cuuint32_t*, const cuuint32_t*,
    CUtensorMapInterleave, CUtensorMapSwizzle, CUtensorMapL2promotion, CUtensorMapFloatOOBfill);

static TmapEncodeFn get_encode_fn()
{
    static TmapEncodeFn fn = nullptr;
    if (!fn) {
        void* p = nullptr;
        cudaDriverEntryPointQueryResult qr;
#if CUDART_VERSION >= 12050
        cudaGetDriverEntryPointByVersion("cuTensorMapEncodeTiled", &p, 12000,
                                         cudaEnableDefault, &qr);
#else
        cudaGetDriverEntryPoint("cuTensorMapEncodeTiled", &p, cudaEnableDefault, &qr);
#endif
        fn = (TmapEncodeFn)p;
    }
    return fn;
}

static void encode_2d(TmapEncodeFn fn, CUtensorMap* m, void* base, unsigned long long rows)
{
    cuuint64_t dims[2]    = {HID, rows};
    cuuint64_t strides[1] = {HID * 2};         // bytes between rows
    cuuint32_t box[2]     = {BK, BM};          // 32 fp16 (64 B) x 128 rows
    cuuint32_t es[2]      = {1, 1};
    fn(m, CU_TENSOR_MAP_DATA_TYPE_FLOAT16, 2, base, dims, strides, box, es,
       CU_TENSOR_MAP_INTERLEAVE_NONE, CU_TENSOR_MAP_SWIZZLE_64B,
       CU_TENSOR_MAP_L2_PROMOTION_L2_128B, CU_TENSOR_MAP_FLOAT_OOB_FILL_NONE);
}

extern "C" void kernel_launch(void* const* d_in, const int* in_sizes, int n_in,
                              void* d_out, int out_size)
{
    const float* x   = (const float*)d_in[0];
    // d_in[1] edge_index, d_in[2] batch: fixed DAG folded into closed-form coefficients
    const float* W1  = (const float*)d_in[3];
    const float* b1  = (const float*)d_in[4];
    const float* W2  = (const float*)d_in[5];
    const float* b2  = (const float*)d_in[6];
    // d_in[7] We, d_in[8] be, d_in[11] g_edge: dead — avg of 2-way softmax == 0.5 exactly
    const float* Wm  = (const float*)d_in[9];
    const float* bm  = (const float*)d_in[10];
    const float* gop = (const float*)d_in[12];
    float* out = (float*)d_out;

    __half *Xsp, *H1sp, *Wsp;
    float* qpart;
    cudaGetSymbolAddress((void**)&Xsp,   g_Xsp);
    cudaGetSymbolAddress((void**)&H1sp,  g_H1sp);
    cudaGetSymbolAddress((void**)&Wsp,   g_Wsp);
    cudaGetSymbolAddress((void**)&qpart, g_qpart);

    TmapEncodeFn fn = get_encode_fn();
    CUtensorMap tX, tH, tW;
    encode_2d(fn, &tX, Xsp,  2ull*MP);   // rows: comp*MP + m
    encode_2d(fn, &tH, H1sp, 2ull*MP);
    encode_2d(fn, &tW, Wsp,  1024ull);   // rows: layer*512 + comp*256 + n

    cudaFuncSetAttribute(gemm_mma, cudaFuncAttributeMaxDynamicSharedMemorySize, SMEM_DYN);

    prep_all<<<NGR + 512, 256>>>(x, W1, W2);

    dim3 grid(HID / BN, MP / BM);        // (2, 1250)
    gemm_mma<<<grid, THREADS, SMEM_DYN>>>(tX, tW, 0,   b1, H1sp,    nullptr, nullptr, 0);
    gemm_mma<<<grid, THREADS, SMEM_DYN>>>(tH, tW, 512, b2, nullptr, Wm,      qpart,   1);

    op_select<<<NN / 224, 224>>>(qpart, bm, gop, out);
}